// round 1
// baseline (speedup 1.0000x reference)
#include <cuda_runtime.h>
#include <cstdint>

// ---------------------------------------------------------------------------
// RWKV forward: L=6, H=1024, A=1024, I=4096, V=50277, B=4, T=2048, fp32
// Round 1: correct fp32 baseline.
//  - GEMMs: 128x128x16 tiles, 8x8 per-thread, NT layout (both operands K-major)
//  - time-mix fused into GEMM A-load; sigmoid/relu^2/residual fused in epilogue
//  - WKV: 3-pass chunked parallel scan (chunk=64)
// ---------------------------------------------------------------------------

#define Ld 6
#define Hd 1024
#define Ad 1024
#define Id 4096
#define Bd 4
#define Td 2048
#define Mdim (Bd*Td)          // 8192 tokens
#define EPSv 1e-5f
#define NEGv -1e38f

#define CHUNK 64
#define NCH (Td/CHUNK)        // 32

// ------------------------- scratch (static, no allocs) ---------------------
__device__ float g_h [Mdim*Hd];
__device__ float g_x [Mdim*Hd];
__device__ float g_k [Mdim*Ad];
__device__ float g_v [Mdim*Ad];
__device__ float g_r [Mdim*Ad];
__device__ float g_y [Mdim*Ad];
__device__ float g_kk[(size_t)Mdim*Id];
__device__ float g_rr[Mdim*Hd];

__device__ float g_sa[Bd*NCH*Ad], g_sb[Bd*NCH*Ad], g_sp[Bd*NCH*Ad];
__device__ float g_ca[Bd*NCH*Ad], g_cb[Bd*NCH*Ad], g_cp[Bd*NCH*Ad];

// ------------------------------- layernorm ---------------------------------
__device__ __forceinline__ void block_reduce2(float& s, float& s2)
{
    #pragma unroll
    for (int o = 16; o > 0; o >>= 1) {
        s  += __shfl_xor_sync(0xffffffffu, s,  o);
        s2 += __shfl_xor_sync(0xffffffffu, s2, o);
    }
    __shared__ float sh[2][8];
    int w = threadIdx.x >> 5, l = threadIdx.x & 31;
    if (l == 0) { sh[0][w] = s; sh[1][w] = s2; }
    __syncthreads();
    if (w == 0) {
        s  = (l < 8) ? sh[0][l] : 0.f;
        s2 = (l < 8) ? sh[1][l] : 0.f;
        #pragma unroll
        for (int o = 4; o > 0; o >>= 1) {
            s  += __shfl_xor_sync(0xffffffffu, s,  o);
            s2 += __shfl_xor_sync(0xffffffffu, s2, o);
        }
        if (l == 0) { sh[0][0] = s; sh[1][0] = s2; }
    }
    __syncthreads();
    s = sh[0][0]; s2 = sh[1][0];
}

// out[row] = LN(in[row]) * w + b      (H=1024, 256 threads, float4 per thread)
__global__ void ln_kernel(const float* __restrict__ in,
                          const float* __restrict__ w,
                          const float* __restrict__ b,
                          float* __restrict__ out)
{
    size_t row = blockIdx.x;
    const float4 v = ((const float4*)(in + row*Hd))[threadIdx.x];
    float s  = v.x + v.y + v.z + v.w;
    float s2 = v.x*v.x + v.y*v.y + v.z*v.z + v.w*v.w;
    block_reduce2(s, s2);
    float mu  = s * (1.f/Hd);
    float var = s2 * (1.f/Hd) - mu*mu;
    float inv = rsqrtf(var + EPSv);
    float4 wv = ((const float4*)w)[threadIdx.x];
    float4 bv = ((const float4*)b)[threadIdx.x];
    float4 o;
    o.x = (v.x - mu)*inv*wv.x + bv.x;
    o.y = (v.y - mu)*inv*wv.y + bv.y;
    o.z = (v.z - mu)*inv*wv.z + bv.z;
    o.w = (v.w - mu)*inv*wv.w + bv.w;
    ((float4*)(out + row*Hd))[threadIdx.x] = o;
}

// embed gather + pre-LN
__global__ void embed_ln_kernel(const int* __restrict__ ids,
                                const float* __restrict__ embed,
                                const float* __restrict__ w,
                                const float* __restrict__ b,
                                float* __restrict__ out)
{
    size_t row = blockIdx.x;
    size_t id  = (size_t)ids[row];
    const float4 v = ((const float4*)(embed + id*Hd))[threadIdx.x];
    float s  = v.x + v.y + v.z + v.w;
    float s2 = v.x*v.x + v.y*v.y + v.z*v.z + v.w*v.w;
    block_reduce2(s, s2);
    float mu  = s * (1.f/Hd);
    float var = s2 * (1.f/Hd) - mu*mu;
    float inv = rsqrtf(var + EPSv);
    float4 wv = ((const float4*)w)[threadIdx.x];
    float4 bv = ((const float4*)b)[threadIdx.x];
    float4 o;
    o.x = (v.x - mu)*inv*wv.x + bv.x;
    o.y = (v.y - mu)*inv*wv.y + bv.y;
    o.z = (v.z - mu)*inv*wv.z + bv.z;
    o.w = (v.w - mu)*inv*wv.w + bv.w;
    ((float4*)(out + row*Hd))[threadIdx.x] = o;
}

// --------------------------------- GEMM ------------------------------------
// C[m,n] = epi( sum_k Aeff[m,k] * B[n,k] )   (both A,B row-major, K contiguous)
// AMODE: 0 plain, 1 time-mix (A2 = mix vector[K], prev row = token t-1),
//        2 elementwise mul (A2 = [M,K])
// EPMODE: 0 store, 1 sigmoid, 2 relu^2, 3 C += acc (residual, in-place),
//         4 C = C + mulsrc*acc
template<int AMODE, int EPMODE>
__global__ __launch_bounds__(256, 2)
void gemm_nt(const float* __restrict__ A, const float* __restrict__ B,
             float* __restrict__ C,
             const float* __restrict__ A2,
             const float* __restrict__ mulsrc,
             int M, int N, int K)
{
    __shared__ float As[16*132];
    __shared__ float Bs[16*132];

    const int m0 = blockIdx.y * 128;
    const int n0 = blockIdx.x * 128;
    const int tid = threadIdx.x;
    const int tx = tid & 15, ty = tid >> 4;
    const int lrow = tid >> 2;       // 0..63
    const int lk4  = (tid & 3) * 4;  // 0,4,8,12

    float acc[8][8];
    #pragma unroll
    for (int i = 0; i < 8; i++)
        #pragma unroll
        for (int j = 0; j < 8; j++) acc[i][j] = 0.f;

    for (int k0 = 0; k0 < K; k0 += 16) {
        #pragma unroll
        for (int hh = 0; hh < 2; hh++) {
            int row = lrow + hh*64;
            // ---- A tile (with optional fusion) ----
            int gm = m0 + row;
            const float* aptr = A + (size_t)gm*K + k0 + lk4;
            float4 av;
            if (AMODE == 1) {
                float4 cur = *(const float4*)aptr;
                float4 prev = make_float4(0.f,0.f,0.f,0.f);
                if ((gm & (Td-1)) != 0) prev = *(const float4*)(aptr - K);
                float4 mx = *(const float4*)(A2 + k0 + lk4);
                av.x = mx.x*cur.x + (1.f-mx.x)*prev.x;
                av.y = mx.y*cur.y + (1.f-mx.y)*prev.y;
                av.z = mx.z*cur.z + (1.f-mx.z)*prev.z;
                av.w = mx.w*cur.w + (1.f-mx.w)*prev.w;
            } else if (AMODE == 2) {
                float4 cur = *(const float4*)aptr;
                float4 mm  = *(const float4*)(A2 + (size_t)gm*K + k0 + lk4);
                av.x = cur.x*mm.x; av.y = cur.y*mm.y;
                av.z = cur.z*mm.z; av.w = cur.w*mm.w;
            } else {
                av = *(const float4*)aptr;
            }
            As[(lk4+0)*132 + row] = av.x;
            As[(lk4+1)*132 + row] = av.y;
            As[(lk4+2)*132 + row] = av.z;
            As[(lk4+3)*132 + row] = av.w;
            // ---- B tile ----
            int gn = n0 + row;
            float4 bv = *(const float4*)(B + (size_t)gn*K + k0 + lk4);
            Bs[(lk4+0)*132 + row] = bv.x;
            Bs[(lk4+1)*132 + row] = bv.y;
            Bs[(lk4+2)*132 + row] = bv.z;
            Bs[(lk4+3)*132 + row] = bv.w;
        }
        __syncthreads();

        #pragma unroll
        for (int kk = 0; kk < 16; kk++) {
            float4 a0 = *(const float4*)&As[kk*132 + ty*8];
            float4 a1 = *(const float4*)&As[kk*132 + ty*8 + 4];
            float4 b0 = *(const float4*)&Bs[kk*132 + tx*8];
            float4 b1 = *(const float4*)&Bs[kk*132 + tx*8 + 4];
            float ar[8] = {a0.x,a0.y,a0.z,a0.w,a1.x,a1.y,a1.z,a1.w};
            float br[8] = {b0.x,b0.y,b0.z,b0.w,b1.x,b1.y,b1.z,b1.w};
            #pragma unroll
            for (int i = 0; i < 8; i++)
                #pragma unroll
                for (int j = 0; j < 8; j++)
                    acc[i][j] = fmaf(ar[i], br[j], acc[i][j]);
        }
        __syncthreads();
    }

    // ---- epilogue ----
    #pragma unroll
    for (int i = 0; i < 8; i++) {
        size_t base = (size_t)(m0 + ty*8 + i)*N + n0 + tx*8;
        #pragma unroll
        for (int jj = 0; jj < 2; jj++) {
            float4 v = make_float4(acc[i][jj*4+0], acc[i][jj*4+1],
                                   acc[i][jj*4+2], acc[i][jj*4+3]);
            if (EPMODE == 1) {
                v.x = 1.f/(1.f+__expf(-v.x)); v.y = 1.f/(1.f+__expf(-v.y));
                v.z = 1.f/(1.f+__expf(-v.z)); v.w = 1.f/(1.f+__expf(-v.w));
            } else if (EPMODE == 2) {
                v.x = fmaxf(v.x,0.f); v.x *= v.x;
                v.y = fmaxf(v.y,0.f); v.y *= v.y;
                v.z = fmaxf(v.z,0.f); v.z *= v.z;
                v.w = fmaxf(v.w,0.f); v.w *= v.w;
            } else if (EPMODE == 3) {
                float4 c = *(const float4*)&C[base + jj*4];
                v.x += c.x; v.y += c.y; v.z += c.z; v.w += c.w;
            } else if (EPMODE == 4) {
                float4 c = *(const float4*)&C[base + jj*4];
                float4 m = *(const float4*)&mulsrc[base + jj*4];
                v.x = c.x + m.x*v.x; v.y = c.y + m.y*v.y;
                v.z = c.z + m.z*v.z; v.w = c.w + m.w*v.w;
            }
            *(float4*)&C[base + jj*4] = v;
        }
    }
}

// ------------------------------- WKV scan ----------------------------------
// Linear recurrence (stabilized): carry (aa,bb,pp); step t:
//   out_t = (aa*e^{pp-q} + e^{u+k-q} v) / (bb*e^{pp-q} + e^{u+k-q}),  q=max(pp,u+k)
//   carry' : q2=max(pp+w,k); aa=e^{pp+w-q2}aa+e^{k-q2}v; bb likewise; pp=q2

__global__ void wkv_pass1(const float* __restrict__ K, const float* __restrict__ V,
                          const float* __restrict__ td)
{
    int bc = blockIdx.x >> 2;             // b*NCH + c
    int a  = (blockIdx.x & 3)*256 + threadIdx.x;
    int b  = bc / NCH, c = bc % NCH;
    float w_ = -__expf(td[a]);
    float aa = 0.f, bb = 0.f, pp = NEGv;
    const float* kp = K + ((size_t)(b*Td + c*CHUNK))*Ad + a;
    const float* vp = V + ((size_t)(b*Td + c*CHUNK))*Ad + a;
    #pragma unroll 4
    for (int t = 0; t < CHUNK; t++) {
        float kt = kp[(size_t)t*Ad], vt = vp[(size_t)t*Ad];
        float q2 = fmaxf(pp + w_, kt);
        float e1 = __expf(pp + w_ - q2), e2 = __expf(kt - q2);
        aa = e1*aa + e2*vt; bb = e1*bb + e2; pp = q2;
    }
    int idx = (b*NCH + c)*Ad + a;
    g_sa[idx] = aa; g_sb[idx] = bb; g_sp[idx] = pp;
}

__global__ void wkv_pass2(const float* __restrict__ td)
{
    int idx = blockIdx.x*256 + threadIdx.x;   // 0..4095
    int b = idx >> 10, a = idx & (Ad-1);
    float w_ = -__expf(td[a]);
    float wC = w_ * (float)CHUNK;
    float aa = 0.f, bb = 0.f, pp = NEGv;
    for (int c = 0; c < NCH; c++) {
        int i = (b*NCH + c)*Ad + a;
        g_ca[i] = aa; g_cb[i] = bb; g_cp[i] = pp;
        float p1 = pp + wC;
        float sa = g_sa[i], sb = g_sb[i], sp = g_sp[i];
        float q  = fmaxf(p1, sp);
        float e1 = __expf(p1 - q), e2 = __expf(sp - q);
        aa = aa*e1 + sa*e2; bb = bb*e1 + sb*e2; pp = q;
    }
}

__global__ void wkv_pass3(const float* __restrict__ K, const float* __restrict__ V,
                          float* __restrict__ Y,
                          const float* __restrict__ td, const float* __restrict__ tf)
{
    int bc = blockIdx.x >> 2;
    int a  = (blockIdx.x & 3)*256 + threadIdx.x;
    int b  = bc / NCH, c = bc % NCH;
    float w_ = -__expf(td[a]);
    float u_ = tf[a];
    int idx = (b*NCH + c)*Ad + a;
    float aa = g_ca[idx], bb = g_cb[idx], pp = g_cp[idx];
    size_t off0 = ((size_t)(b*Td + c*CHUNK))*Ad + a;
    #pragma unroll 4
    for (int t = 0; t < CHUNK; t++) {
        size_t off = off0 + (size_t)t*Ad;
        float kt = K[off], vt = V[off];
        float uk = u_ + kt;
        float q  = fmaxf(pp, uk);
        float e1 = __expf(uk - q), e2 = __expf(pp - q);
        Y[off] = (aa*e2 + e1*vt) / (bb*e2 + e1);
        float q2 = fmaxf(pp + w_, kt);
        float s1 = __expf(pp + w_ - q2), s2 = __expf(kt - q2);
        aa = s1*aa + s2*vt; bb = s1*bb + s2; pp = q2;
    }
}

// ------------------------------- driver ------------------------------------
extern "C" void kernel_launch(void* const* d_in, const int* in_sizes, int n_in,
                              void* d_out, int out_size)
{
    const int*   ids       = (const int*)  d_in[0];
    const float* embed     = (const float*)d_in[1];
    const float* pre_ln_w  = (const float*)d_in[2];
    const float* pre_ln_b  = (const float*)d_in[3];
    const float* post_ln_w = (const float*)d_in[4];
    const float* post_ln_b = (const float*)d_in[5];
    const float* ln1_w     = (const float*)d_in[6];
    const float* ln1_b     = (const float*)d_in[7];
    const float* ln2_w     = (const float*)d_in[8];
    const float* ln2_b     = (const float*)d_in[9];
    const float* mix_k     = (const float*)d_in[10];
    const float* mix_v     = (const float*)d_in[11];
    const float* mix_r     = (const float*)d_in[12];
    const float* att_wk    = (const float*)d_in[13];
    const float* att_wv    = (const float*)d_in[14];
    const float* att_wr    = (const float*)d_in[15];
    const float* att_wo    = (const float*)d_in[16];
    const float* time_decay= (const float*)d_in[17];
    const float* time_first= (const float*)d_in[18];
    const float* fmix_k    = (const float*)d_in[19];
    const float* fmix_r    = (const float*)d_in[20];
    const float* ffn_wk    = (const float*)d_in[21];
    const float* ffn_wr    = (const float*)d_in[22];
    const float* ffn_wv    = (const float*)d_in[23];

    float* out = (float*)d_out;

    float *h, *x, *k, *v, *r, *y, *kk, *rr;
    cudaGetSymbolAddress((void**)&h,  g_h);
    cudaGetSymbolAddress((void**)&x,  g_x);
    cudaGetSymbolAddress((void**)&k,  g_k);
    cudaGetSymbolAddress((void**)&v,  g_v);
    cudaGetSymbolAddress((void**)&r,  g_r);
    cudaGetSymbolAddress((void**)&y,  g_y);
    cudaGetSymbolAddress((void**)&kk, g_kk);
    cudaGetSymbolAddress((void**)&rr, g_rr);

    dim3 t256(256);
    dim3 gH(Hd/128, Mdim/128);      // N=1024
    dim3 gI(Id/128, Mdim/128);      // N=4096

    embed_ln_kernel<<<Mdim, t256>>>(ids, embed, pre_ln_w, pre_ln_b, h);

    for (int i = 0; i < Ld; i++) {
        const float* wk = att_wk + (size_t)i*Ad*Hd;
        const float* wv = att_wv + (size_t)i*Ad*Hd;
        const float* wr = att_wr + (size_t)i*Ad*Hd;
        const float* wo = att_wo + (size_t)i*Hd*Ad;
        const float* td = time_decay + (size_t)i*Ad;
        const float* tf = time_first + (size_t)i*Ad;

        ln_kernel<<<Mdim, t256>>>(h, ln1_w + (size_t)i*Hd, ln1_b + (size_t)i*Hd, x);

        gemm_nt<1,0><<<gH, t256>>>(x, wk, k, mix_k + (size_t)i*Hd, nullptr, Mdim, Ad, Hd);
        gemm_nt<1,0><<<gH, t256>>>(x, wv, v, mix_v + (size_t)i*Hd, nullptr, Mdim, Ad, Hd);
        gemm_nt<1,1><<<gH, t256>>>(x, wr, r, mix_r + (size_t)i*Hd, nullptr, Mdim, Ad, Hd);

        wkv_pass1<<<Bd*NCH*4, t256>>>(k, v, td);
        wkv_pass2<<<16, t256>>>(td);
        wkv_pass3<<<Bd*NCH*4, t256>>>(k, v, y, td, tf);

        // h += (r*y) @ wo^T
        gemm_nt<2,3><<<gH, t256>>>(y, wo, h, r, nullptr, Mdim, Hd, Ad);

        ln_kernel<<<Mdim, t256>>>(h, ln2_w + (size_t)i*Hd, ln2_b + (size_t)i*Hd, x);

        // kk = relu(mix @ ffn_wk^T)^2 ; rr = sigmoid(mix @ ffn_wr^T)
        gemm_nt<1,2><<<gI, t256>>>(x, ffn_wk + (size_t)i*Id*Hd, kk,
                                   fmix_k + (size_t)i*Hd, nullptr, Mdim, Id, Hd);
        gemm_nt<1,1><<<gH, t256>>>(x, ffn_wr + (size_t)i*Hd*Hd, rr,
                                   fmix_r + (size_t)i*Hd, nullptr, Mdim, Hd, Hd);
        // h += rr * (kk @ ffn_wv^T)
        gemm_nt<0,4><<<gH, t256>>>(kk, ffn_wv + (size_t)i*Hd*Id, h,
                                   nullptr, rr, Mdim, Hd, Id);
    }

    ln_kernel<<<Mdim, t256>>>(h, post_ln_w, post_ln_b, out);
}

// round 2
// speedup vs baseline: 2.1246x; 2.1246x over previous
#include <cuda_runtime.h>
#include <cstdint>

// ---------------------------------------------------------------------------
// RWKV forward: L=6, H=1024, A=1024, I=4096, V=50277, B=4, T=2048, fp32
// Round 2: TF32 tensor-core GEMMs (mma.sync m16n8k8), fused prologue/epilogue.
// ---------------------------------------------------------------------------

#define Ld 6
#define Hd 1024
#define Ad 1024
#define Id 4096
#define Bd 4
#define Td 2048
#define Mdim (Bd*Td)          // 8192 tokens
#define EPSv 1e-5f
#define NEGv -1e38f

#define CHUNK 64
#define NCH (Td/CHUNK)        // 32

// ------------------------- scratch (static, no allocs) ---------------------
__device__ float g_h [Mdim*Hd];
__device__ float g_x [Mdim*Hd];
__device__ float g_k [Mdim*Ad];
__device__ float g_v [Mdim*Ad];
__device__ float g_r [Mdim*Ad];
__device__ float g_y [Mdim*Ad];
__device__ float g_kk[(size_t)Mdim*Id];
__device__ float g_rr[Mdim*Hd];

__device__ float g_sa[Bd*NCH*Ad], g_sb[Bd*NCH*Ad], g_sp[Bd*NCH*Ad];
__device__ float g_ca[Bd*NCH*Ad], g_cb[Bd*NCH*Ad], g_cp[Bd*NCH*Ad];

// ------------------------------- layernorm ---------------------------------
__device__ __forceinline__ void block_reduce2(float& s, float& s2)
{
    #pragma unroll
    for (int o = 16; o > 0; o >>= 1) {
        s  += __shfl_xor_sync(0xffffffffu, s,  o);
        s2 += __shfl_xor_sync(0xffffffffu, s2, o);
    }
    __shared__ float sh[2][8];
    int w = threadIdx.x >> 5, l = threadIdx.x & 31;
    if (l == 0) { sh[0][w] = s; sh[1][w] = s2; }
    __syncthreads();
    if (w == 0) {
        s  = (l < 8) ? sh[0][l] : 0.f;
        s2 = (l < 8) ? sh[1][l] : 0.f;
        #pragma unroll
        for (int o = 4; o > 0; o >>= 1) {
            s  += __shfl_xor_sync(0xffffffffu, s,  o);
            s2 += __shfl_xor_sync(0xffffffffu, s2, o);
        }
        if (l == 0) { sh[0][0] = s; sh[1][0] = s2; }
    }
    __syncthreads();
    s = sh[0][0]; s2 = sh[1][0];
}

__global__ void ln_kernel(const float* __restrict__ in,
                          const float* __restrict__ w,
                          const float* __restrict__ b,
                          float* __restrict__ out)
{
    size_t row = blockIdx.x;
    const float4 v = ((const float4*)(in + row*Hd))[threadIdx.x];
    float s  = v.x + v.y + v.z + v.w;
    float s2 = v.x*v.x + v.y*v.y + v.z*v.z + v.w*v.w;
    block_reduce2(s, s2);
    float mu  = s * (1.f/Hd);
    float var = s2 * (1.f/Hd) - mu*mu;
    float inv = rsqrtf(var + EPSv);
    float4 wv = ((const float4*)w)[threadIdx.x];
    float4 bv = ((const float4*)b)[threadIdx.x];
    float4 o;
    o.x = (v.x - mu)*inv*wv.x + bv.x;
    o.y = (v.y - mu)*inv*wv.y + bv.y;
    o.z = (v.z - mu)*inv*wv.z + bv.z;
    o.w = (v.w - mu)*inv*wv.w + bv.w;
    ((float4*)(out + row*Hd))[threadIdx.x] = o;
}

__global__ void embed_ln_kernel(const int* __restrict__ ids,
                                const float* __restrict__ embed,
                                const float* __restrict__ w,
                                const float* __restrict__ b,
                                float* __restrict__ out)
{
    size_t row = blockIdx.x;
    size_t id  = (size_t)ids[row];
    const float4 v = ((const float4*)(embed + id*Hd))[threadIdx.x];
    float s  = v.x + v.y + v.z + v.w;
    float s2 = v.x*v.x + v.y*v.y + v.z*v.z + v.w*v.w;
    block_reduce2(s, s2);
    float mu  = s * (1.f/Hd);
    float var = s2 * (1.f/Hd) - mu*mu;
    float inv = rsqrtf(var + EPSv);
    float4 wv = ((const float4*)w)[threadIdx.x];
    float4 bv = ((const float4*)b)[threadIdx.x];
    float4 o;
    o.x = (v.x - mu)*inv*wv.x + bv.x;
    o.y = (v.y - mu)*inv*wv.y + bv.y;
    o.z = (v.z - mu)*inv*wv.z + bv.z;
    o.w = (v.w - mu)*inv*wv.w + bv.w;
    ((float4*)(out + row*Hd))[threadIdx.x] = o;
}

// ------------------------------ TF32 helpers --------------------------------
__device__ __forceinline__ uint32_t f2tf(float f)
{
    uint32_t u;
    asm("cvt.rna.tf32.f32 %0, %1;" : "=r"(u) : "f"(f));
    return u;
}

__device__ __forceinline__ void mma_tf32(float* c, const uint32_t* a, const uint32_t* b)
{
    asm volatile(
        "mma.sync.aligned.m16n8k8.row.col.f32.tf32.tf32.f32 "
        "{%0,%1,%2,%3}, {%4,%5,%6,%7}, {%8,%9}, {%0,%1,%2,%3};"
        : "+f"(c[0]), "+f"(c[1]), "+f"(c[2]), "+f"(c[3])
        : "r"(a[0]), "r"(a[1]), "r"(a[2]), "r"(a[3]),
          "r"(b[0]), "r"(b[1]));
}

// ------------------------------ TF32 GEMM -----------------------------------
// C[m,n] = epi( sum_k Aeff[m,k] * B[n,k] )   (both row-major, K contiguous)
// AMODE: 0 plain, 1 time-mix (A2 = mix vec[K], prev = token t-1), 2 A*A2 elemwise
// EPMODE: 0 store, 1 sigmoid, 2 relu^2, 3 C+=acc, 4 C = C + mulsrc*acc
// CTA 128x128, BK=32, warp tile 64x32 (4x(m16) x 4x(n8)), 8 warps.
#define SLD 36   // smem row stride in floats (conflict-free fragment reads)

template<int AMODE, int EPMODE>
__global__ __launch_bounds__(256, 1)
void gemm_tc(const float* __restrict__ A, const float* __restrict__ B,
             float* __restrict__ C,
             const float* __restrict__ A2,
             const float* __restrict__ mulsrc,
             int M, int N, int K)
{
    __shared__ __align__(16) float As[128*SLD];
    __shared__ __align__(16) float Bs[128*SLD];

    const int m0 = blockIdx.y * 128;
    const int n0 = blockIdx.x * 128;
    const int tid  = threadIdx.x;
    const int lane = tid & 31;
    const int wid  = tid >> 5;
    const int g  = lane >> 2;     // 0..7
    const int cc = lane & 3;      // 0..3
    const int wm0 = (wid >> 2) * 64;   // 0,64
    const int wn0 = (wid & 3) * 32;    // 0,32,64,96
    const int arow = tid >> 3;    // 0..31 (+32*i)
    const int akq  = tid & 7;     // float4 index within 32-float row

    float acc[4][4][4];
    #pragma unroll
    for (int i = 0; i < 4; i++)
        #pragma unroll
        for (int j = 0; j < 4; j++)
            #pragma unroll
            for (int q = 0; q < 4; q++) acc[i][j][q] = 0.f;

    float4 ra[4], rb[4];

    auto stage_load = [&](int it) {
        const int kc = it*32 + akq*4;
        #pragma unroll
        for (int i2 = 0; i2 < 4; i2++) {
            const int row = arow + 32*i2;
            {   // A (with fusion)
                const int gm = m0 + row;
                const float* p = A + (size_t)gm*K + kc;
                float4 cur = *(const float4*)p;
                if (AMODE == 1) {
                    float4 prev = make_float4(0.f,0.f,0.f,0.f);
                    if (gm & (Td-1)) prev = *(const float4*)(p - K);
                    float4 mx = *(const float4*)(A2 + kc);
                    cur.x = mx.x*cur.x + (1.f-mx.x)*prev.x;
                    cur.y = mx.y*cur.y + (1.f-mx.y)*prev.y;
                    cur.z = mx.z*cur.z + (1.f-mx.z)*prev.z;
                    cur.w = mx.w*cur.w + (1.f-mx.w)*prev.w;
                } else if (AMODE == 2) {
                    float4 mm = *(const float4*)(A2 + (size_t)gm*K + kc);
                    cur.x *= mm.x; cur.y *= mm.y; cur.z *= mm.z; cur.w *= mm.w;
                }
                ra[i2] = cur;
            }
            {   // B
                const int gn = n0 + row;
                rb[i2] = *(const float4*)(B + (size_t)gn*K + kc);
            }
        }
    };

    auto stage_store = [&]() {
        #pragma unroll
        for (int i2 = 0; i2 < 4; i2++) {
            const int row = arow + 32*i2;
            uint4 ua; ua.x = f2tf(ra[i2].x); ua.y = f2tf(ra[i2].y);
                      ua.z = f2tf(ra[i2].z); ua.w = f2tf(ra[i2].w);
            *(uint4*)(As + row*SLD + akq*4) = ua;
            uint4 ub; ub.x = f2tf(rb[i2].x); ub.y = f2tf(rb[i2].y);
                      ub.z = f2tf(rb[i2].z); ub.w = f2tf(rb[i2].w);
            *(uint4*)(Bs + row*SLD + akq*4) = ub;
        }
    };

    stage_load(0);
    stage_store();
    __syncthreads();

    const int iters = K >> 5;
    for (int it = 0; it < iters; it++) {
        if (it + 1 < iters) stage_load(it + 1);  // overlaps MMA below

        const uint32_t* AsU = (const uint32_t*)As;
        const uint32_t* BsU = (const uint32_t*)Bs;
        #pragma unroll
        for (int kb = 0; kb < 4; kb++) {
            const int k0 = kb*8;
            uint32_t af[4][4], bf[4][2];
            #pragma unroll
            for (int i = 0; i < 4; i++) {
                const int r = wm0 + i*16;
                af[i][0] = AsU[(r+g  )*SLD + k0 + cc    ];
                af[i][1] = AsU[(r+g+8)*SLD + k0 + cc    ];
                af[i][2] = AsU[(r+g  )*SLD + k0 + cc + 4];
                af[i][3] = AsU[(r+g+8)*SLD + k0 + cc + 4];
            }
            #pragma unroll
            for (int j = 0; j < 4; j++) {
                const int r = wn0 + j*8 + g;
                bf[j][0] = BsU[r*SLD + k0 + cc    ];
                bf[j][1] = BsU[r*SLD + k0 + cc + 4];
            }
            #pragma unroll
            for (int i = 0; i < 4; i++)
                #pragma unroll
                for (int j = 0; j < 4; j++)
                    mma_tf32(acc[i][j], af[i], bf[j]);
        }
        __syncthreads();
        if (it + 1 < iters) {
            stage_store();
            __syncthreads();
        }
    }

    // ---- epilogue ----
    #pragma unroll
    for (int i = 0; i < 4; i++) {
        #pragma unroll
        for (int j = 0; j < 4; j++) {
            #pragma unroll
            for (int hh = 0; hh < 2; hh++) {
                const int row = m0 + wm0 + i*16 + g + hh*8;
                const int col = n0 + wn0 + j*8 + 2*cc;
                float vx = acc[i][j][hh*2 + 0];
                float vy = acc[i][j][hh*2 + 1];
                const size_t off = (size_t)row*N + col;
                if (EPMODE == 1) {
                    vx = 1.f/(1.f + __expf(-vx));
                    vy = 1.f/(1.f + __expf(-vy));
                } else if (EPMODE == 2) {
                    vx = fmaxf(vx, 0.f); vx *= vx;
                    vy = fmaxf(vy, 0.f); vy *= vy;
                } else if (EPMODE == 3) {
                    float2 c = *(const float2*)&C[off];
                    vx += c.x; vy += c.y;
                } else if (EPMODE == 4) {
                    float2 c = *(const float2*)&C[off];
                    float2 m = *(const float2*)&mulsrc[off];
                    vx = c.x + m.x*vx; vy = c.y + m.y*vy;
                }
                *(float2*)&C[off] = make_float2(vx, vy);
            }
        }
    }
}

// ------------------------------- WKV scan ----------------------------------
__global__ void wkv_pass1(const float* __restrict__ K, const float* __restrict__ V,
                          const float* __restrict__ td)
{
    int bc = blockIdx.x >> 2;
    int a  = (blockIdx.x & 3)*256 + threadIdx.x;
    int b  = bc / NCH, c = bc % NCH;
    float w_ = -__expf(td[a]);
    float aa = 0.f, bb = 0.f, pp = NEGv;
    const float* kp = K + ((size_t)(b*Td + c*CHUNK))*Ad + a;
    const float* vp = V + ((size_t)(b*Td + c*CHUNK))*Ad + a;
    #pragma unroll 4
    for (int t = 0; t < CHUNK; t++) {
        float kt = kp[(size_t)t*Ad], vt = vp[(size_t)t*Ad];
        float q2 = fmaxf(pp + w_, kt);
        float e1 = __expf(pp + w_ - q2), e2 = __expf(kt - q2);
        aa = e1*aa + e2*vt; bb = e1*bb + e2; pp = q2;
    }
    int idx = (b*NCH + c)*Ad + a;
    g_sa[idx] = aa; g_sb[idx] = bb; g_sp[idx] = pp;
}

__global__ void wkv_pass2(const float* __restrict__ td)
{
    int idx = blockIdx.x*256 + threadIdx.x;   // 0..4095
    int b = idx >> 10, a = idx & (Ad-1);
    float w_ = -__expf(td[a]);
    float wC = w_ * (float)CHUNK;
    float aa = 0.f, bb = 0.f, pp = NEGv;
    for (int c = 0; c < NCH; c++) {
        int i = (b*NCH + c)*Ad + a;
        g_ca[i] = aa; g_cb[i] = bb; g_cp[i] = pp;
        float p1 = pp + wC;
        float sa = g_sa[i], sb = g_sb[i], sp = g_sp[i];
        float q  = fmaxf(p1, sp);
        float e1 = __expf(p1 - q), e2 = __expf(sp - q);
        aa = aa*e1 + sa*e2; bb = bb*e1 + sb*e2; pp = q;
    }
}

__global__ void wkv_pass3(const float* __restrict__ K, const float* __restrict__ V,
                          float* __restrict__ Y,
                          const float* __restrict__ td, const float* __restrict__ tf)
{
    int bc = blockIdx.x >> 2;
    int a  = (blockIdx.x & 3)*256 + threadIdx.x;
    int b  = bc / NCH, c = bc % NCH;
    float w_ = -__expf(td[a]);
    float u_ = tf[a];
    int idx = (b*NCH + c)*Ad + a;
    float aa = g_ca[idx], bb = g_cb[idx], pp = g_cp[idx];
    size_t off0 = ((size_t)(b*Td + c*CHUNK))*Ad + a;
    #pragma unroll 4
    for (int t = 0; t < CHUNK; t++) {
        size_t off = off0 + (size_t)t*Ad;
        float kt = K[off], vt = V[off];
        float uk = u_ + kt;
        float q  = fmaxf(pp, uk);
        float e1 = __expf(uk - q), e2 = __expf(pp - q);
        Y[off] = (aa*e2 + e1*vt) / (bb*e2 + e1);
        float q2 = fmaxf(pp + w_, kt);
        float s1 = __expf(pp + w_ - q2), s2 = __expf(kt - q2);
        aa = s1*aa + s2*vt; bb = s1*bb + s2; pp = q2;
    }
}

// ------------------------------- driver ------------------------------------
extern "C" void kernel_launch(void* const* d_in, const int* in_sizes, int n_in,
                              void* d_out, int out_size)
{
    const int*   ids       = (const int*)  d_in[0];
    const float* embed     = (const float*)d_in[1];
    const float* pre_ln_w  = (const float*)d_in[2];
    const float* pre_ln_b  = (const float*)d_in[3];
    const float* post_ln_w = (const float*)d_in[4];
    const float* post_ln_b = (const float*)d_in[5];
    const float* ln1_w     = (const float*)d_in[6];
    const float* ln1_b     = (const float*)d_in[7];
    const float* ln2_w     = (const float*)d_in[8];
    const float* ln2_b     = (const float*)d_in[9];
    const float* mix_k     = (const float*)d_in[10];
    const float* mix_v     = (const float*)d_in[11];
    const float* mix_r     = (const float*)d_in[12];
    const float* att_wk    = (const float*)d_in[13];
    const float* att_wv    = (const float*)d_in[14];
    const float* att_wr    = (const float*)d_in[15];
    const float* att_wo    = (const float*)d_in[16];
    const float* time_decay= (const float*)d_in[17];
    const float* time_first= (const float*)d_in[18];
    const float* fmix_k    = (const float*)d_in[19];
    const float* fmix_r    = (const float*)d_in[20];
    const float* ffn_wk    = (const float*)d_in[21];
    const float* ffn_wr    = (const float*)d_in[22];
    const float* ffn_wv    = (const float*)d_in[23];

    float* out = (float*)d_out;

    float *h, *x, *k, *v, *r, *y, *kk, *rr;
    cudaGetSymbolAddress((void**)&h,  g_h);
    cudaGetSymbolAddress((void**)&x,  g_x);
    cudaGetSymbolAddress((void**)&k,  g_k);
    cudaGetSymbolAddress((void**)&v,  g_v);
    cudaGetSymbolAddress((void**)&r,  g_r);
    cudaGetSymbolAddress((void**)&y,  g_y);
    cudaGetSymbolAddress((void**)&kk, g_kk);
    cudaGetSymbolAddress((void**)&rr, g_rr);

    dim3 t256(256);
    dim3 gH(Hd/128, Mdim/128);      // N=1024
    dim3 gI(Id/128, Mdim/128);      // N=4096

    embed_ln_kernel<<<Mdim, t256>>>(ids, embed, pre_ln_w, pre_ln_b, h);

    for (int i = 0; i < Ld; i++) {
        const float* wk = att_wk + (size_t)i*Ad*Hd;
        const float* wv = att_wv + (size_t)i*Ad*Hd;
        const float* wr = att_wr + (size_t)i*Ad*Hd;
        const float* wo = att_wo + (size_t)i*Hd*Ad;
        const float* td = time_decay + (size_t)i*Ad;
        const float* tf = time_first + (size_t)i*Ad;

        ln_kernel<<<Mdim, t256>>>(h, ln1_w + (size_t)i*Hd, ln1_b + (size_t)i*Hd, x);

        gemm_tc<1,0><<<gH, t256>>>(x, wk, k, mix_k + (size_t)i*Hd, nullptr, Mdim, Ad, Hd);
        gemm_tc<1,0><<<gH, t256>>>(x, wv, v, mix_v + (size_t)i*Hd, nullptr, Mdim, Ad, Hd);
        gemm_tc<1,1><<<gH, t256>>>(x, wr, r, mix_r + (size_t)i*Hd, nullptr, Mdim, Ad, Hd);

        wkv_pass1<<<Bd*NCH*4, t256>>>(k, v, td);
        wkv_pass2<<<16, t256>>>(td);
        wkv_pass3<<<Bd*NCH*4, t256>>>(k, v, y, td, tf);

        // h += (r*y) @ wo^T
        gemm_tc<2,3><<<gH, t256>>>(y, wo, h, r, nullptr, Mdim, Hd, Ad);

        ln_kernel<<<Mdim, t256>>>(h, ln2_w + (size_t)i*Hd, ln2_b + (size_t)i*Hd, x);

        // kk = relu(mix @ ffn_wk^T)^2 ; rr = sigmoid(mix @ ffn_wr^T)
        gemm_tc<1,2><<<gI, t256>>>(x, ffn_wk + (size_t)i*Id*Hd, kk,
                                   fmix_k + (size_t)i*Hd, nullptr, Mdim, Id, Hd);
        gemm_tc<1,1><<<gH, t256>>>(x, ffn_wr + (size_t)i*Hd*Hd, rr,
                                   fmix_r + (size_t)i*Hd, nullptr, Mdim, Hd, Hd);
        // h += rr * (kk @ ffn_wv^T)
        gemm_tc<0,4><<<gH, t256>>>(kk, ffn_wv + (size_t)i*Hd*Id, h,
                                   nullptr, rr, Mdim, Hd, Id);
    }

    ln_kernel<<<Mdim, t256>>>(h, post_ln_w, post_ln_b, out);
}

// round 3
// speedup vs baseline: 2.4069x; 1.1328x over previous
#include <cuda_runtime.h>
#include <cstdint>

// ---------------------------------------------------------------------------
// RWKV forward: L=6, H=1024, A=1024, I=4096, B=4, T=2048, fp32
// Round 3: TF32 mma.sync + cp.async 2-stage pipeline, pre-rounded operands,
//          fused LN+time-mix producers, 2 CTAs/SM.
// ---------------------------------------------------------------------------

#define Ld 6
#define Hd 1024
#define Ad 1024
#define Id 4096
#define Bd 4
#define Td 2048
#define Mdim (Bd*Td)          // 8192 tokens
#define EPSv 1e-5f
#define NEGv -1e38f

#define CHUNK 64
#define NCH (Td/CHUNK)        // 32

#define SLD 36                // smem row stride (floats), conflict-free frags
#define SMEM_BYTES (2*2*128*SLD*4)   // 2 stages x (A+B) x 128 x SLD floats

// ------------------------- scratch (static, no allocs) ---------------------
__device__ float g_h [Mdim*Hd];
__device__ float g_k [Mdim*Ad];
__device__ float g_v [Mdim*Ad];
__device__ float g_r [Mdim*Ad];
__device__ float g_y [Mdim*Ad];
__device__ float g_kk[(size_t)Mdim*Id];
__device__ float g_rr[Mdim*Hd];
__device__ float g_xk[Mdim*Hd];
__device__ float g_xv[Mdim*Hd];
__device__ float g_xr[Mdim*Hd];

// tf32-rounded weight copies
__device__ float g_cwk [Ld*Ad*Hd];
__device__ float g_cwv [Ld*Ad*Hd];
__device__ float g_cwr [Ld*Ad*Hd];
__device__ float g_cwo [Ld*Hd*Ad];
__device__ float g_cfwk[(size_t)Ld*Id*Hd];
__device__ float g_cfwr[Ld*Hd*Hd];
__device__ float g_cfwv[(size_t)Ld*Hd*Id];

__device__ float g_sa[Bd*NCH*Ad], g_sb[Bd*NCH*Ad], g_sp[Bd*NCH*Ad];
__device__ float g_ca[Bd*NCH*Ad], g_cb[Bd*NCH*Ad], g_cp[Bd*NCH*Ad];

// ------------------------------ helpers -------------------------------------
__device__ __forceinline__ uint32_t f2tf(float f)
{
    uint32_t u;
    asm("cvt.rna.tf32.f32 %0, %1;" : "=r"(u) : "f"(f));
    return u;
}
__device__ __forceinline__ float rtf(float f) { return __uint_as_float(f2tf(f)); }

__device__ __forceinline__ void mma_tf32(float* c, const uint32_t* a, const uint32_t* b)
{
    asm volatile(
        "mma.sync.aligned.m16n8k8.row.col.f32.tf32.tf32.f32 "
        "{%0,%1,%2,%3}, {%4,%5,%6,%7}, {%8,%9}, {%0,%1,%2,%3};"
        : "+f"(c[0]), "+f"(c[1]), "+f"(c[2]), "+f"(c[3])
        : "r"(a[0]), "r"(a[1]), "r"(a[2]), "r"(a[3]),
          "r"(b[0]), "r"(b[1]));
}

__device__ __forceinline__ void cp16(uint32_t dst, const void* src)
{
    asm volatile("cp.async.cg.shared.global [%0], [%1], 16;\n"
                 :: "r"(dst), "l"(src));
}

// weight tf32 pre-rounding (grid-stride over float4)
__global__ void round_tf32(const float* __restrict__ in, float* __restrict__ out,
                           size_t n4)
{
    size_t i = (size_t)blockIdx.x*blockDim.x + threadIdx.x;
    if (i >= n4) return;
    float4 v = ((const float4*)in)[i];
    v.x = rtf(v.x); v.y = rtf(v.y); v.z = rtf(v.z); v.w = rtf(v.w);
    ((float4*)out)[i] = v;
}

// ----------------------------- reductions -----------------------------------
__device__ __forceinline__ void block_reduce4(float& a, float& b, float& c, float& d)
{
    #pragma unroll
    for (int o = 16; o > 0; o >>= 1) {
        a += __shfl_xor_sync(0xffffffffu, a, o);
        b += __shfl_xor_sync(0xffffffffu, b, o);
        c += __shfl_xor_sync(0xffffffffu, c, o);
        d += __shfl_xor_sync(0xffffffffu, d, o);
    }
    __shared__ float sh[4][8];
    int w = threadIdx.x >> 5, l = threadIdx.x & 31;
    if (l == 0) { sh[0][w] = a; sh[1][w] = b; sh[2][w] = c; sh[3][w] = d; }
    __syncthreads();
    if (w == 0) {
        a = (l < 8) ? sh[0][l] : 0.f;
        b = (l < 8) ? sh[1][l] : 0.f;
        c = (l < 8) ? sh[2][l] : 0.f;
        d = (l < 8) ? sh[3][l] : 0.f;
        #pragma unroll
        for (int o = 4; o > 0; o >>= 1) {
            a += __shfl_xor_sync(0xffffffffu, a, o);
            b += __shfl_xor_sync(0xffffffffu, b, o);
            c += __shfl_xor_sync(0xffffffffu, c, o);
            d += __shfl_xor_sync(0xffffffffu, d, o);
        }
        if (l == 0) { sh[0][0] = a; sh[1][0] = b; sh[2][0] = c; sh[3][0] = d; }
    }
    __syncthreads();
    a = sh[0][0]; b = sh[1][0]; c = sh[2][0]; d = sh[3][0];
}

// plain LN (post / final)
__global__ void ln_kernel(const float* __restrict__ in,
                          const float* __restrict__ w,
                          const float* __restrict__ b,
                          float* __restrict__ out)
{
    size_t row = blockIdx.x;
    const float4 v = ((const float4*)(in + row*Hd))[threadIdx.x];
    float s  = v.x + v.y + v.z + v.w;
    float s2 = v.x*v.x + v.y*v.y + v.z*v.z + v.w*v.w;
    float z0 = 0.f, z1 = 0.f;
    block_reduce4(s, s2, z0, z1);
    float mu  = s * (1.f/Hd);
    float inv = rsqrtf(s2*(1.f/Hd) - mu*mu + EPSv);
    float4 wv = ((const float4*)w)[threadIdx.x];
    float4 bv = ((const float4*)b)[threadIdx.x];
    float4 o;
    o.x = (v.x - mu)*inv*wv.x + bv.x;
    o.y = (v.y - mu)*inv*wv.y + bv.y;
    o.z = (v.z - mu)*inv*wv.z + bv.z;
    o.w = (v.w - mu)*inv*wv.w + bv.w;
    ((float4*)(out + row*Hd))[threadIdx.x] = o;
}

__global__ void embed_ln_kernel(const int* __restrict__ ids,
                                const float* __restrict__ embed,
                                const float* __restrict__ w,
                                const float* __restrict__ b,
                                float* __restrict__ out)
{
    size_t row = blockIdx.x;
    size_t id  = (size_t)ids[row];
    const float4 v = ((const float4*)(embed + id*Hd))[threadIdx.x];
    float s  = v.x + v.y + v.z + v.w;
    float s2 = v.x*v.x + v.y*v.y + v.z*v.z + v.w*v.w;
    float z0 = 0.f, z1 = 0.f;
    block_reduce4(s, s2, z0, z1);
    float mu  = s * (1.f/Hd);
    float inv = rsqrtf(s2*(1.f/Hd) - mu*mu + EPSv);
    float4 wv = ((const float4*)w)[threadIdx.x];
    float4 bv = ((const float4*)b)[threadIdx.x];
    float4 o;
    o.x = (v.x - mu)*inv*wv.x + bv.x;
    o.y = (v.y - mu)*inv*wv.y + bv.y;
    o.z = (v.z - mu)*inv*wv.z + bv.z;
    o.w = (v.w - mu)*inv*wv.w + bv.w;
    ((float4*)(out + row*Hd))[threadIdx.x] = o;
}

// fused LN + time-mix (3 outputs, att) — writes tf32-rounded mixes
__global__ void ln_mix3(const float* __restrict__ hsrc,
                        const float* __restrict__ lw, const float* __restrict__ lb,
                        const float* __restrict__ mk, const float* __restrict__ mv,
                        const float* __restrict__ mr,
                        float* __restrict__ xk, float* __restrict__ xv,
                        float* __restrict__ xr)
{
    size_t row = blockIdx.x;
    int t = threadIdx.x;
    bool hp = (row & (Td-1)) != 0;
    float4 cur = ((const float4*)(hsrc + row*Hd))[t];
    float4 prv = make_float4(0.f,0.f,0.f,0.f);
    if (hp) prv = ((const float4*)(hsrc + (row-1)*Hd))[t];
    float s1 = cur.x+cur.y+cur.z+cur.w;
    float q1 = cur.x*cur.x+cur.y*cur.y+cur.z*cur.z+cur.w*cur.w;
    float s2 = prv.x+prv.y+prv.z+prv.w;
    float q2 = prv.x*prv.x+prv.y*prv.y+prv.z*prv.z+prv.w*prv.w;
    block_reduce4(s1, q1, s2, q2);
    float mu1 = s1*(1.f/Hd), inv1 = rsqrtf(q1*(1.f/Hd) - mu1*mu1 + EPSv);
    float mu2 = s2*(1.f/Hd), inv2 = rsqrtf(q2*(1.f/Hd) - mu2*mu2 + EPSv);
    float4 wv = ((const float4*)lw)[t];
    float4 bv = ((const float4*)lb)[t];
    float4 xc, xp;
    xc.x = (cur.x-mu1)*inv1*wv.x + bv.x;  xc.y = (cur.y-mu1)*inv1*wv.y + bv.y;
    xc.z = (cur.z-mu1)*inv1*wv.z + bv.z;  xc.w = (cur.w-mu1)*inv1*wv.w + bv.w;
    if (hp) {
        xp.x = (prv.x-mu2)*inv2*wv.x + bv.x;  xp.y = (prv.y-mu2)*inv2*wv.y + bv.y;
        xp.z = (prv.z-mu2)*inv2*wv.z + bv.z;  xp.w = (prv.w-mu2)*inv2*wv.w + bv.w;
    } else xp = make_float4(0.f,0.f,0.f,0.f);

    float4 m, o;
    m = ((const float4*)mk)[t];
    o.x = rtf(m.x*xc.x + (1.f-m.x)*xp.x); o.y = rtf(m.y*xc.y + (1.f-m.y)*xp.y);
    o.z = rtf(m.z*xc.z + (1.f-m.z)*xp.z); o.w = rtf(m.w*xc.w + (1.f-m.w)*xp.w);
    ((float4*)(xk + row*Hd))[t] = o;
    m = ((const float4*)mv)[t];
    o.x = rtf(m.x*xc.x + (1.f-m.x)*xp.x); o.y = rtf(m.y*xc.y + (1.f-m.y)*xp.y);
    o.z = rtf(m.z*xc.z + (1.f-m.z)*xp.z); o.w = rtf(m.w*xc.w + (1.f-m.w)*xp.w);
    ((float4*)(xv + row*Hd))[t] = o;
    m = ((const float4*)mr)[t];
    o.x = rtf(m.x*xc.x + (1.f-m.x)*xp.x); o.y = rtf(m.y*xc.y + (1.f-m.y)*xp.y);
    o.z = rtf(m.z*xc.z + (1.f-m.z)*xp.z); o.w = rtf(m.w*xc.w + (1.f-m.w)*xp.w);
    ((float4*)(xr + row*Hd))[t] = o;
}

// fused LN + channel-mix (2 outputs, ffn)
__global__ void ln_mix2(const float* __restrict__ hsrc,
                        const float* __restrict__ lw, const float* __restrict__ lb,
                        const float* __restrict__ mk, const float* __restrict__ mr,
                        float* __restrict__ xk, float* __restrict__ xr)
{
    size_t row = blockIdx.x;
    int t = threadIdx.x;
    bool hp = (row & (Td-1)) != 0;
    float4 cur = ((const float4*)(hsrc + row*Hd))[t];
    float4 prv = make_float4(0.f,0.f,0.f,0.f);
    if (hp) prv = ((const float4*)(hsrc + (row-1)*Hd))[t];
    float s1 = cur.x+cur.y+cur.z+cur.w;
    float q1 = cur.x*cur.x+cur.y*cur.y+cur.z*cur.z+cur.w*cur.w;
    float s2 = prv.x+prv.y+prv.z+prv.w;
    float q2 = prv.x*prv.x+prv.y*prv.y+prv.z*prv.z+prv.w*prv.w;
    block_reduce4(s1, q1, s2, q2);
    float mu1 = s1*(1.f/Hd), inv1 = rsqrtf(q1*(1.f/Hd) - mu1*mu1 + EPSv);
    float mu2 = s2*(1.f/Hd), inv2 = rsqrtf(q2*(1.f/Hd) - mu2*mu2 + EPSv);
    float4 wv = ((const float4*)lw)[t];
    float4 bv = ((const float4*)lb)[t];
    float4 xc, xp;
    xc.x = (cur.x-mu1)*inv1*wv.x + bv.x;  xc.y = (cur.y-mu1)*inv1*wv.y + bv.y;
    xc.z = (cur.z-mu1)*inv1*wv.z + bv.z;  xc.w = (cur.w-mu1)*inv1*wv.w + bv.w;
    if (hp) {
        xp.x = (prv.x-mu2)*inv2*wv.x + bv.x;  xp.y = (prv.y-mu2)*inv2*wv.y + bv.y;
        xp.z = (prv.z-mu2)*inv2*wv.z + bv.z;  xp.w = (prv.w-mu2)*inv2*wv.w + bv.w;
    } else xp = make_float4(0.f,0.f,0.f,0.f);

    float4 m, o;
    m = ((const float4*)mk)[t];
    o.x = rtf(m.x*xc.x + (1.f-m.x)*xp.x); o.y = rtf(m.y*xc.y + (1.f-m.y)*xp.y);
    o.z = rtf(m.z*xc.z + (1.f-m.z)*xp.z); o.w = rtf(m.w*xc.w + (1.f-m.w)*xp.w);
    ((float4*)(xk + row*Hd))[t] = o;
    m = ((const float4*)mr)[t];
    o.x = rtf(m.x*xc.x + (1.f-m.x)*xp.x); o.y = rtf(m.y*xc.y + (1.f-m.y)*xp.y);
    o.z = rtf(m.z*xc.z + (1.f-m.z)*xp.z); o.w = rtf(m.w*xc.w + (1.f-m.w)*xp.w);
    ((float4*)(xr + row*Hd))[t] = o;
}

// ------------------------------ TF32 GEMM -----------------------------------
// C[m,n] = epi( sum_k A[m,k]*B[n,k] ); A,B pre-rounded to tf32 values.
// EPMODE: 0 store, 1 sigmoid, 2 tf32(relu^2), 3 C+=acc, 4 C = C + mulsrc*acc
template<int EPMODE>
__global__ __launch_bounds__(256, 2)
void gemm_tc(const float* __restrict__ A, const float* __restrict__ B,
             float* __restrict__ C, const float* __restrict__ mulsrc,
             int M, int N, int K)
{
    extern __shared__ float smem[];
    float* As = smem;                  // [2][128*SLD]
    float* Bs = smem + 2*128*SLD;

    const int m0 = blockIdx.y * 128;
    const int n0 = blockIdx.x * 128;
    const int tid  = threadIdx.x;
    const int lane = tid & 31;
    const int wid  = tid >> 5;
    const int g  = lane >> 2;
    const int cc = lane & 3;
    const int wm0 = (wid >> 2) * 64;
    const int wn0 = (wid & 3) * 32;
    const int lrow = tid >> 1;          // 0..127
    const int lq0  = (tid & 1) * 16;    // float offset within 32-float row

    const uint32_t sAu = (uint32_t)__cvta_generic_to_shared(As);
    const uint32_t sBu = (uint32_t)__cvta_generic_to_shared(Bs);

    float acc[4][4][4];
    #pragma unroll
    for (int i = 0; i < 4; i++)
        #pragma unroll
        for (int j = 0; j < 4; j++)
            #pragma unroll
            for (int q = 0; q < 4; q++) acc[i][j][q] = 0.f;

    const float* agp = A + (size_t)(m0 + lrow)*K + lq0;
    const float* bgp = B + (size_t)(n0 + lrow)*K + lq0;

    auto load_stage = [&](int it, int st) {
        const int kc = it*32;
        uint32_t da = sAu + (uint32_t)((st*128*SLD + lrow*SLD + lq0) * 4);
        uint32_t db = sBu + (uint32_t)((st*128*SLD + lrow*SLD + lq0) * 4);
        #pragma unroll
        for (int q = 0; q < 4; q++) {
            cp16(da + q*16, agp + kc + q*4);
            cp16(db + q*16, bgp + kc + q*4);
        }
    };

    const int iters = K >> 5;
    load_stage(0, 0);
    asm volatile("cp.async.commit_group;\n" ::: "memory");
    load_stage(1, 1);
    asm volatile("cp.async.commit_group;\n" ::: "memory");

    for (int it = 0; it < iters; it++) {
        asm volatile("cp.async.wait_group 1;\n" ::: "memory");
        __syncthreads();

        const int st = it & 1;
        const uint32_t* AsU = (const uint32_t*)(As + st*128*SLD);
        const uint32_t* BsU = (const uint32_t*)(Bs + st*128*SLD);
        #pragma unroll
        for (int kb = 0; kb < 4; kb++) {
            const int k0 = kb*8;
            uint32_t af[4][4], bf[4][2];
            #pragma unroll
            for (int i = 0; i < 4; i++) {
                const int rr_ = wm0 + i*16;
                af[i][0] = AsU[(rr_+g  )*SLD + k0 + cc    ];
                af[i][1] = AsU[(rr_+g+8)*SLD + k0 + cc    ];
                af[i][2] = AsU[(rr_+g  )*SLD + k0 + cc + 4];
                af[i][3] = AsU[(rr_+g+8)*SLD + k0 + cc + 4];
            }
            #pragma unroll
            for (int j = 0; j < 4; j++) {
                const int rr_ = wn0 + j*8 + g;
                bf[j][0] = BsU[rr_*SLD + k0 + cc    ];
                bf[j][1] = BsU[rr_*SLD + k0 + cc + 4];
            }
            #pragma unroll
            for (int i = 0; i < 4; i++)
                #pragma unroll
                for (int j = 0; j < 4; j++)
                    mma_tf32(acc[i][j], af[i], bf[j]);
        }
        __syncthreads();
        if (it + 2 < iters) load_stage(it + 2, st);
        asm volatile("cp.async.commit_group;\n" ::: "memory");
    }

    // ---- epilogue ----
    #pragma unroll
    for (int i = 0; i < 4; i++) {
        #pragma unroll
        for (int j = 0; j < 4; j++) {
            #pragma unroll
            for (int hh = 0; hh < 2; hh++) {
                const int row = m0 + wm0 + i*16 + g + hh*8;
                const int col = n0 + wn0 + j*8 + 2*cc;
                float vx = acc[i][j][hh*2 + 0];
                float vy = acc[i][j][hh*2 + 1];
                const size_t off = (size_t)row*N + col;
                if (EPMODE == 1) {
                    vx = 1.f/(1.f + __expf(-vx));
                    vy = 1.f/(1.f + __expf(-vy));
                } else if (EPMODE == 2) {
                    vx = fmaxf(vx, 0.f); vx = rtf(vx*vx);
                    vy = fmaxf(vy, 0.f); vy = rtf(vy*vy);
                } else if (EPMODE == 3) {
                    float2 c = *(const float2*)&C[off];
                    vx += c.x; vy += c.y;
                } else if (EPMODE == 4) {
                    float2 c = *(const float2*)&C[off];
                    float2 m = *(const float2*)&mulsrc[off];
                    vx = c.x + m.x*vx; vy = c.y + m.y*vy;
                }
                *(float2*)&C[off] = make_float2(vx, vy);
            }
        }
    }
}

// ------------------------------- WKV scan ----------------------------------
__global__ void wkv_pass1(const float* __restrict__ K, const float* __restrict__ V,
                          const float* __restrict__ td)
{
    int bc = blockIdx.x >> 2;
    int a  = (blockIdx.x & 3)*256 + threadIdx.x;
    int b  = bc / NCH, c = bc % NCH;
    float w_ = -__expf(td[a]);
    float aa = 0.f, bb = 0.f, pp = NEGv;
    const float* kp = K + ((size_t)(b*Td + c*CHUNK))*Ad + a;
    const float* vp = V + ((size_t)(b*Td + c*CHUNK))*Ad + a;
    #pragma unroll 4
    for (int t = 0; t < CHUNK; t++) {
        float kt = kp[(size_t)t*Ad], vt = vp[(size_t)t*Ad];
        float q2 = fmaxf(pp + w_, kt);
        float e1 = __expf(pp + w_ - q2), e2 = __expf(kt - q2);
        aa = e1*aa + e2*vt; bb = e1*bb + e2; pp = q2;
    }
    int idx = (b*NCH + c)*Ad + a;
    g_sa[idx] = aa; g_sb[idx] = bb; g_sp[idx] = pp;
}

__global__ void wkv_pass2(const float* __restrict__ td)
{
    int idx = blockIdx.x*256 + threadIdx.x;   // 0..4095
    int b = idx >> 10, a = idx & (Ad-1);
    float w_ = -__expf(td[a]);
    float wC = w_ * (float)CHUNK;
    float aa = 0.f, bb = 0.f, pp = NEGv;
    for (int c = 0; c < NCH; c++) {
        int i = (b*NCH + c)*Ad + a;
        g_ca[i] = aa; g_cb[i] = bb; g_cp[i] = pp;
        float p1 = pp + wC;
        float sa = g_sa[i], sb = g_sb[i], sp = g_sp[i];
        float q  = fmaxf(p1, sp);
        float e1 = __expf(p1 - q), e2 = __expf(sp - q);
        aa = aa*e1 + sa*e2; bb = bb*e1 + sb*e2; pp = q;
    }
}

// pass3 also multiplies by r and tf32-rounds (output feeds wo GEMM as A)
__global__ void wkv_pass3(const float* __restrict__ K, const float* __restrict__ V,
                          const float* __restrict__ R, float* __restrict__ Y,
                          const float* __restrict__ td, const float* __restrict__ tf)
{
    int bc = blockIdx.x >> 2;
    int a  = (blockIdx.x & 3)*256 + threadIdx.x;
    int b  = bc / NCH, c = bc % NCH;
    float w_ = -__expf(td[a]);
    float u_ = tf[a];
    int idx = (b*NCH + c)*Ad + a;
    float aa = g_ca[idx], bb = g_cb[idx], pp = g_cp[idx];
    size_t off0 = ((size_t)(b*Td + c*CHUNK))*Ad + a;
    #pragma unroll 4
    for (int t = 0; t < CHUNK; t++) {
        size_t off = off0 + (size_t)t*Ad;
        float kt = K[off], vt = V[off];
        float uk = u_ + kt;
        float q  = fmaxf(pp, uk);
        float e1 = __expf(uk - q), e2 = __expf(pp - q);
        float outv = (aa*e2 + e1*vt) / (bb*e2 + e1);
        Y[off] = rtf(R[off] * outv);
        float q2 = fmaxf(pp + w_, kt);
        float s1 = __expf(pp + w_ - q2), s2 = __expf(kt - q2);
        aa = s1*aa + s2*vt; bb = s1*bb + s2; pp = q2;
    }
}

// ------------------------------- driver ------------------------------------
extern "C" void kernel_launch(void* const* d_in, const int* in_sizes, int n_in,
                              void* d_out, int out_size)
{
    const int*   ids       = (const int*)  d_in[0];
    const float* embed     = (const float*)d_in[1];
    const float* pre_ln_w  = (const float*)d_in[2];
    const float* pre_ln_b  = (const float*)d_in[3];
    const float* post_ln_w = (const float*)d_in[4];
    const float* post_ln_b = (const float*)d_in[5];
    const float* ln1_w     = (const float*)d_in[6];
    const float* ln1_b     = (const float*)d_in[7];
    const float* ln2_w     = (const float*)d_in[8];
    const float* ln2_b     = (const float*)d_in[9];
    const float* mix_k     = (const float*)d_in[10];
    const float* mix_v     = (const float*)d_in[11];
    const float* mix_r     = (const float*)d_in[12];
    const float* att_wk    = (const float*)d_in[13];
    const float* att_wv    = (const float*)d_in[14];
    const float* att_wr    = (const float*)d_in[15];
    const float* att_wo    = (const float*)d_in[16];
    const float* time_decay= (const float*)d_in[17];
    const float* time_first= (const float*)d_in[18];
    const float* fmix_k    = (const float*)d_in[19];
    const float* fmix_r    = (const float*)d_in[20];
    const float* ffn_wk    = (const float*)d_in[21];
    const float* ffn_wr    = (const float*)d_in[22];
    const float* ffn_wv    = (const float*)d_in[23];

    float* out = (float*)d_out;

    float *h, *k, *v, *r, *y, *kk, *rr, *xk, *xv, *xr;
    float *cwk, *cwv, *cwr, *cwo, *cfwk, *cfwr, *cfwv;
    cudaGetSymbolAddress((void**)&h,  g_h);
    cudaGetSymbolAddress((void**)&k,  g_k);
    cudaGetSymbolAddress((void**)&v,  g_v);
    cudaGetSymbolAddress((void**)&r,  g_r);
    cudaGetSymbolAddress((void**)&y,  g_y);
    cudaGetSymbolAddress((void**)&kk, g_kk);
    cudaGetSymbolAddress((void**)&rr, g_rr);
    cudaGetSymbolAddress((void**)&xk, g_xk);
    cudaGetSymbolAddress((void**)&xv, g_xv);
    cudaGetSymbolAddress((void**)&xr, g_xr);
    cudaGetSymbolAddress((void**)&cwk,  g_cwk);
    cudaGetSymbolAddress((void**)&cwv,  g_cwv);
    cudaGetSymbolAddress((void**)&cwr,  g_cwr);
    cudaGetSymbolAddress((void**)&cwo,  g_cwo);
    cudaGetSymbolAddress((void**)&cfwk, g_cfwk);
    cudaGetSymbolAddress((void**)&cfwr, g_cfwr);
    cudaGetSymbolAddress((void**)&cfwv, g_cfwv);

    static bool attr_done = false;
    if (!attr_done) {
        cudaFuncSetAttribute(gemm_tc<0>, cudaFuncAttributeMaxDynamicSharedMemorySize, SMEM_BYTES);
        cudaFuncSetAttribute(gemm_tc<1>, cudaFuncAttributeMaxDynamicSharedMemorySize, SMEM_BYTES);
        cudaFuncSetAttribute(gemm_tc<2>, cudaFuncAttributeMaxDynamicSharedMemorySize, SMEM_BYTES);
        cudaFuncSetAttribute(gemm_tc<3>, cudaFuncAttributeMaxDynamicSharedMemorySize, SMEM_BYTES);
        cudaFuncSetAttribute(gemm_tc<4>, cudaFuncAttributeMaxDynamicSharedMemorySize, SMEM_BYTES);
        attr_done = true;
    }

    dim3 t256(256);
    dim3 gH(Hd/128, Mdim/128);      // N=1024
    dim3 gI(Id/128, Mdim/128);      // N=4096

    // weight pre-rounding (once per replay; ~100us)
    {
        const int TPB = 256;
        size_t n4;
        n4 = (size_t)Ld*Ad*Hd/4;
        round_tf32<<<(unsigned)((n4+TPB-1)/TPB), TPB>>>(att_wk, cwk, n4);
        round_tf32<<<(unsigned)((n4+TPB-1)/TPB), TPB>>>(att_wv, cwv, n4);
        round_tf32<<<(unsigned)((n4+TPB-1)/TPB), TPB>>>(att_wr, cwr, n4);
        round_tf32<<<(unsigned)((n4+TPB-1)/TPB), TPB>>>(att_wo, cwo, n4);
        n4 = (size_t)Ld*Id*Hd/4;
        round_tf32<<<(unsigned)((n4+TPB-1)/TPB), TPB>>>(ffn_wk, cfwk, n4);
        round_tf32<<<(unsigned)((n4+TPB-1)/TPB), TPB>>>(ffn_wv, cfwv, n4);
        n4 = (size_t)Ld*Hd*Hd/4;
        round_tf32<<<(unsigned)((n4+TPB-1)/TPB), TPB>>>(ffn_wr, cfwr, n4);
    }

    embed_ln_kernel<<<Mdim, t256>>>(ids, embed, pre_ln_w, pre_ln_b, h);

    for (int i = 0; i < Ld; i++) {
        const float* td = time_decay + (size_t)i*Ad;
        const float* tf = time_first + (size_t)i*Ad;

        ln_mix3<<<Mdim, t256>>>(h, ln1_w + (size_t)i*Hd, ln1_b + (size_t)i*Hd,
                                mix_k + (size_t)i*Hd, mix_v + (size_t)i*Hd,
                                mix_r + (size_t)i*Hd, xk, xv, xr);

        gemm_tc<0><<<gH, t256, SMEM_BYTES>>>(xk, cwk + (size_t)i*Ad*Hd, k, nullptr, Mdim, Ad, Hd);
        gemm_tc<0><<<gH, t256, SMEM_BYTES>>>(xv, cwv + (size_t)i*Ad*Hd, v, nullptr, Mdim, Ad, Hd);
        gemm_tc<1><<<gH, t256, SMEM_BYTES>>>(xr, cwr + (size_t)i*Ad*Hd, r, nullptr, Mdim, Ad, Hd);

        wkv_pass1<<<Bd*NCH*4, t256>>>(k, v, td);
        wkv_pass2<<<16, t256>>>(td);
        wkv_pass3<<<Bd*NCH*4, t256>>>(k, v, r, y, td, tf);

        // h += (r*y) @ wo^T   (y already holds tf32(r*y))
        gemm_tc<3><<<gH, t256, SMEM_BYTES>>>(y, cwo + (size_t)i*Hd*Ad, h, nullptr, Mdim, Hd, Ad);

        ln_mix2<<<Mdim, t256>>>(h, ln2_w + (size_t)i*Hd, ln2_b + (size_t)i*Hd,
                                fmix_k + (size_t)i*Hd, fmix_r + (size_t)i*Hd, xk, xr);

        gemm_tc<2><<<gI, t256, SMEM_BYTES>>>(xk, cfwk + (size_t)i*Id*Hd, kk, nullptr, Mdim, Id, Hd);
        gemm_tc<1><<<gH, t256, SMEM_BYTES>>>(xr, cfwr + (size_t)i*Hd*Hd, rr, nullptr, Mdim, Hd, Hd);
        gemm_tc<4><<<gH, t256, SMEM_BYTES>>>(kk, cfwv + (size_t)i*Hd*Id, h, rr, Mdim, Hd, Id);
    }

    ln_kernel<<<Mdim, t256>>>(h, post_ln_w, post_ln_b, out);
}

// round 6
// speedup vs baseline: 2.6037x; 1.0818x over previous
#include <cuda_runtime.h>
#include <cstdint>

// ---------------------------------------------------------------------------
// RWKV forward: L=6, H=1024, A=1024, I=4096, B=4, T=2048, fp32
// Round 6 (= R5 resubmit after infra failure): TF32 mma.sync + ldmatrix
// fragment loads + cp.async 2-stage, pre-rounded operands, fused LN+mix
// producers, 2 CTAs/SM.  (tcgen05 unavailable: harness targets compute_103)
// ---------------------------------------------------------------------------

#define Ld 6
#define Hd 1024
#define Ad 1024
#define Id 4096
#define Bd 4
#define Td 2048
#define Mdim (Bd*Td)          // 8192 tokens
#define EPSv 1e-5f
#define NEGv -1e38f

#define CHUNK 64
#define NCH (Td/CHUNK)        // 32

#define SLD 36                // smem row stride (floats), conflict-free frags
#define SMEM_BYTES (2*2*128*SLD*4)   // 2 stages x (A+B) x 128 x SLD floats

// ------------------------- scratch (static, no allocs) ---------------------
__device__ float g_h [Mdim*Hd];
__device__ float g_k [Mdim*Ad];
__device__ float g_v [Mdim*Ad];
__device__ float g_r [Mdim*Ad];
__device__ float g_y [Mdim*Ad];
__device__ float g_kk[(size_t)Mdim*Id];
__device__ float g_rr[Mdim*Hd];
__device__ float g_xk[Mdim*Hd];
__device__ float g_xv[Mdim*Hd];
__device__ float g_xr[Mdim*Hd];

// tf32-rounded weight copies
__device__ float g_cwk [Ld*Ad*Hd];
__device__ float g_cwv [Ld*Ad*Hd];
__device__ float g_cwr [Ld*Ad*Hd];
__device__ float g_cwo [Ld*Hd*Ad];
__device__ float g_cfwk[(size_t)Ld*Id*Hd];
__device__ float g_cfwr[Ld*Hd*Hd];
__device__ float g_cfwv[(size_t)Ld*Hd*Id];

__device__ float g_sa[Bd*NCH*Ad], g_sb[Bd*NCH*Ad], g_sp[Bd*NCH*Ad];
__device__ float g_ca[Bd*NCH*Ad], g_cb[Bd*NCH*Ad], g_cp[Bd*NCH*Ad];

// ------------------------------ helpers -------------------------------------
__device__ __forceinline__ uint32_t f2tf(float f)
{
    uint32_t u;
    asm("cvt.rna.tf32.f32 %0, %1;" : "=r"(u) : "f"(f));
    return u;
}
__device__ __forceinline__ float rtf(float f) { return __uint_as_float(f2tf(f)); }

__device__ __forceinline__ void mma_tf32(float* c, const uint32_t* a, const uint32_t* b)
{
    asm volatile(
        "mma.sync.aligned.m16n8k8.row.col.f32.tf32.tf32.f32 "
        "{%0,%1,%2,%3}, {%4,%5,%6,%7}, {%8,%9}, {%0,%1,%2,%3};"
        : "+f"(c[0]), "+f"(c[1]), "+f"(c[2]), "+f"(c[3])
        : "r"(a[0]), "r"(a[1]), "r"(a[2]), "r"(a[3]),
          "r"(b[0]), "r"(b[1]));
}

__device__ __forceinline__ void cp16(uint32_t dst, const void* src)
{
    asm volatile("cp.async.cg.shared.global [%0], [%1], 16;\n"
                 :: "r"(dst), "l"(src));
}

__device__ __forceinline__ void ldsm4(uint32_t* r, uint32_t addr)
{
    asm volatile("ldmatrix.sync.aligned.m8n8.x4.shared.b16 {%0,%1,%2,%3}, [%4];"
                 : "=r"(r[0]), "=r"(r[1]), "=r"(r[2]), "=r"(r[3])
                 : "r"(addr));
}

// weight tf32 pre-rounding (grid-stride over float4)
__global__ void round_tf32(const float* __restrict__ in, float* __restrict__ out,
                           size_t n4)
{
    size_t i = (size_t)blockIdx.x*blockDim.x + threadIdx.x;
    if (i >= n4) return;
    float4 v = ((const float4*)in)[i];
    v.x = rtf(v.x); v.y = rtf(v.y); v.z = rtf(v.z); v.w = rtf(v.w);
    ((float4*)out)[i] = v;
}

// ----------------------------- reductions -----------------------------------
__device__ __forceinline__ void block_reduce4(float& a, float& b, float& c, float& d)
{
    #pragma unroll
    for (int o = 16; o > 0; o >>= 1) {
        a += __shfl_xor_sync(0xffffffffu, a, o);
        b += __shfl_xor_sync(0xffffffffu, b, o);
        c += __shfl_xor_sync(0xffffffffu, c, o);
        d += __shfl_xor_sync(0xffffffffu, d, o);
    }
    __shared__ float sh[4][8];
    int w = threadIdx.x >> 5, l = threadIdx.x & 31;
    if (l == 0) { sh[0][w] = a; sh[1][w] = b; sh[2][w] = c; sh[3][w] = d; }
    __syncthreads();
    if (w == 0) {
        a = (l < 8) ? sh[0][l] : 0.f;
        b = (l < 8) ? sh[1][l] : 0.f;
        c = (l < 8) ? sh[2][l] : 0.f;
        d = (l < 8) ? sh[3][l] : 0.f;
        #pragma unroll
        for (int o = 4; o > 0; o >>= 1) {
            a += __shfl_xor_sync(0xffffffffu, a, o);
            b += __shfl_xor_sync(0xffffffffu, b, o);
            c += __shfl_xor_sync(0xffffffffu, c, o);
            d += __shfl_xor_sync(0xffffffffu, d, o);
        }
        if (l == 0) { sh[0][0] = a; sh[1][0] = b; sh[2][0] = c; sh[3][0] = d; }
    }
    __syncthreads();
    a = sh[0][0]; b = sh[1][0]; c = sh[2][0]; d = sh[3][0];
}

// plain LN (final)
__global__ void ln_kernel(const float* __restrict__ in,
                          const float* __restrict__ w,
                          const float* __restrict__ b,
                          float* __restrict__ out)
{
    size_t row = blockIdx.x;
    const float4 v = ((const float4*)(in + row*Hd))[threadIdx.x];
    float s  = v.x + v.y + v.z + v.w;
    float s2 = v.x*v.x + v.y*v.y + v.z*v.z + v.w*v.w;
    float z0 = 0.f, z1 = 0.f;
    block_reduce4(s, s2, z0, z1);
    float mu  = s * (1.f/Hd);
    float inv = rsqrtf(s2*(1.f/Hd) - mu*mu + EPSv);
    float4 wv = ((const float4*)w)[threadIdx.x];
    float4 bv = ((const float4*)b)[threadIdx.x];
    float4 o;
    o.x = (v.x - mu)*inv*wv.x + bv.x;
    o.y = (v.y - mu)*inv*wv.y + bv.y;
    o.z = (v.z - mu)*inv*wv.z + bv.z;
    o.w = (v.w - mu)*inv*wv.w + bv.w;
    ((float4*)(out + row*Hd))[threadIdx.x] = o;
}

__global__ void embed_ln_kernel(const int* __restrict__ ids,
                                const float* __restrict__ embed,
                                const float* __restrict__ w,
                                const float* __restrict__ b,
                                float* __restrict__ out)
{
    size_t row = blockIdx.x;
    size_t id  = (size_t)ids[row];
    const float4 v = ((const float4*)(embed + id*Hd))[threadIdx.x];
    float s  = v.x + v.y + v.z + v.w;
    float s2 = v.x*v.x + v.y*v.y + v.z*v.z + v.w*v.w;
    float z0 = 0.f, z1 = 0.f;
    block_reduce4(s, s2, z0, z1);
    float mu  = s * (1.f/Hd);
    float inv = rsqrtf(s2*(1.f/Hd) - mu*mu + EPSv);
    float4 wv = ((const float4*)w)[threadIdx.x];
    float4 bv = ((const float4*)b)[threadIdx.x];
    float4 o;
    o.x = (v.x - mu)*inv*wv.x + bv.x;
    o.y = (v.y - mu)*inv*wv.y + bv.y;
    o.z = (v.z - mu)*inv*wv.z + bv.z;
    o.w = (v.w - mu)*inv*wv.w + bv.w;
    ((float4*)(out + row*Hd))[threadIdx.x] = o;
}

// fused LN + time-mix (3 outputs, att) — writes tf32-rounded mixes
__global__ void ln_mix3(const float* __restrict__ hsrc,
                        const float* __restrict__ lw, const float* __restrict__ lb,
                        const float* __restrict__ mk, const float* __restrict__ mv,
                        const float* __restrict__ mr,
                        float* __restrict__ xk, float* __restrict__ xv,
                        float* __restrict__ xr)
{
    size_t row = blockIdx.x;
    int t = threadIdx.x;
    bool hp = (row & (Td-1)) != 0;
    float4 cur = ((const float4*)(hsrc + row*Hd))[t];
    float4 prv = make_float4(0.f,0.f,0.f,0.f);
    if (hp) prv = ((const float4*)(hsrc + (row-1)*Hd))[t];
    float s1 = cur.x+cur.y+cur.z+cur.w;
    float q1 = cur.x*cur.x+cur.y*cur.y+cur.z*cur.z+cur.w*cur.w;
    float s2 = prv.x+prv.y+prv.z+prv.w;
    float q2 = prv.x*prv.x+prv.y*prv.y+prv.z*prv.z+prv.w*prv.w;
    block_reduce4(s1, q1, s2, q2);
    float mu1 = s1*(1.f/Hd), inv1 = rsqrtf(q1*(1.f/Hd) - mu1*mu1 + EPSv);
    float mu2 = s2*(1.f/Hd), inv2 = rsqrtf(q2*(1.f/Hd) - mu2*mu2 + EPSv);
    float4 wv = ((const float4*)lw)[t];
    float4 bv = ((const float4*)lb)[t];
    float4 xc, xp;
    xc.x = (cur.x-mu1)*inv1*wv.x + bv.x;  xc.y = (cur.y-mu1)*inv1*wv.y + bv.y;
    xc.z = (cur.z-mu1)*inv1*wv.z + bv.z;  xc.w = (cur.w-mu1)*inv1*wv.w + bv.w;
    if (hp) {
        xp.x = (prv.x-mu2)*inv2*wv.x + bv.x;  xp.y = (prv.y-mu2)*inv2*wv.y + bv.y;
        xp.z = (prv.z-mu2)*inv2*wv.z + bv.z;  xp.w = (prv.w-mu2)*inv2*wv.w + bv.w;
    } else xp = make_float4(0.f,0.f,0.f,0.f);

    float4 m, o;
    m = ((const float4*)mk)[t];
    o.x = rtf(m.x*xc.x + (1.f-m.x)*xp.x); o.y = rtf(m.y*xc.y + (1.f-m.y)*xp.y);
    o.z = rtf(m.z*xc.z + (1.f-m.z)*xp.z); o.w = rtf(m.w*xc.w + (1.f-m.w)*xp.w);
    ((float4*)(xk + row*Hd))[t] = o;
    m = ((const float4*)mv)[t];
    o.x = rtf(m.x*xc.x + (1.f-m.x)*xp.x); o.y = rtf(m.y*xc.y + (1.f-m.y)*xp.y);
    o.z = rtf(m.z*xc.z + (1.f-m.z)*xp.z); o.w = rtf(m.w*xc.w + (1.f-m.w)*xp.w);
    ((float4*)(xv + row*Hd))[t] = o;
    m = ((const float4*)mr)[t];
    o.x = rtf(m.x*xc.x + (1.f-m.x)*xp.x); o.y = rtf(m.y*xc.y + (1.f-m.y)*xp.y);
    o.z = rtf(m.z*xc.z + (1.f-m.z)*xp.z); o.w = rtf(m.w*xc.w + (1.f-m.w)*xp.w);
    ((float4*)(xr + row*Hd))[t] = o;
}

// fused LN + channel-mix (2 outputs, ffn)
__global__ void ln_mix2(const float* __restrict__ hsrc,
                        const float* __restrict__ lw, const float* __restrict__ lb,
                        const float* __restrict__ mk, const float* __restrict__ mr,
                        float* __restrict__ xk, float* __restrict__ xr)
{
    size_t row = blockIdx.x;
    int t = threadIdx.x;
    bool hp = (row & (Td-1)) != 0;
    float4 cur = ((const float4*)(hsrc + row*Hd))[t];
    float4 prv = make_float4(0.f,0.f,0.f,0.f);
    if (hp) prv = ((const float4*)(hsrc + (row-1)*Hd))[t];
    float s1 = cur.x+cur.y+cur.z+cur.w;
    float q1 = cur.x*cur.x+cur.y*cur.y+cur.z*cur.z+cur.w*cur.w;
    float s2 = prv.x+prv.y+prv.z+prv.w;
    float q2 = prv.x*prv.x+prv.y*prv.y+prv.z*prv.z+prv.w*prv.w;
    block_reduce4(s1, q1, s2, q2);
    float mu1 = s1*(1.f/Hd), inv1 = rsqrtf(q1*(1.f/Hd) - mu1*mu1 + EPSv);
    float mu2 = s2*(1.f/Hd), inv2 = rsqrtf(q2*(1.f/Hd) - mu2*mu2 + EPSv);
    float4 wv = ((const float4*)lw)[t];
    float4 bv = ((const float4*)lb)[t];
    float4 xc, xp;
    xc.x = (cur.x-mu1)*inv1*wv.x + bv.x;  xc.y = (cur.y-mu1)*inv1*wv.y + bv.y;
    xc.z = (cur.z-mu1)*inv1*wv.z + bv.z;  xc.w = (cur.w-mu1)*inv1*wv.w + bv.w;
    if (hp) {
        xp.x = (prv.x-mu2)*inv2*wv.x + bv.x;  xp.y = (prv.y-mu2)*inv2*wv.y + bv.y;
        xp.z = (prv.z-mu2)*inv2*wv.z + bv.z;  xp.w = (prv.w-mu2)*inv2*wv.w + bv.w;
    } else xp = make_float4(0.f,0.f,0.f,0.f);

    float4 m, o;
    m = ((const float4*)mk)[t];
    o.x = rtf(m.x*xc.x + (1.f-m.x)*xp.x); o.y = rtf(m.y*xc.y + (1.f-m.y)*xp.y);
    o.z = rtf(m.z*xc.z + (1.f-m.z)*xp.z); o.w = rtf(m.w*xc.w + (1.f-m.w)*xp.w);
    ((float4*)(xk + row*Hd))[t] = o;
    m = ((const float4*)mr)[t];
    o.x = rtf(m.x*xc.x + (1.f-m.x)*xp.x); o.y = rtf(m.y*xc.y + (1.f-m.y)*xp.y);
    o.z = rtf(m.z*xc.z + (1.f-m.z)*xp.z); o.w = rtf(m.w*xc.w + (1.f-m.w)*xp.w);
    ((float4*)(xr + row*Hd))[t] = o;
}

// ------------------------------ TF32 GEMM -----------------------------------
// C[m,n] = epi( sum_k A[m,k]*B[n,k] ); A,B pre-rounded to tf32 values.
// EPMODE: 0 store, 1 sigmoid, 2 tf32(relu^2), 3 C+=acc, 4 C = C + mulsrc*acc
// CTA 128x128, BK=32, warp tile 64x32, 8 warps, ldmatrix fragment loads.
template<int EPMODE>
__global__ __launch_bounds__(256, 2)
void gemm_tc(const float* __restrict__ A, const float* __restrict__ B,
             float* __restrict__ C, const float* __restrict__ mulsrc,
             int M, int N, int K)
{
    extern __shared__ float smem[];
    float* As = smem;                  // [2][128*SLD]
    float* Bs = smem + 2*128*SLD;

    const int m0 = blockIdx.y * 128;
    const int n0 = blockIdx.x * 128;
    const int tid  = threadIdx.x;
    const int lane = tid & 31;
    const int wid  = tid >> 5;
    const int g  = lane >> 2;
    const int cc = lane & 3;
    const int wm0 = (wid >> 2) * 64;
    const int wn0 = (wid & 3) * 32;
    const int lrow = tid >> 1;          // 0..127
    const int lq0  = (tid & 1) * 16;    // float offset within 32-float row

    const uint32_t sAu = (uint32_t)__cvta_generic_to_shared(As);
    const uint32_t sBu = (uint32_t)__cvta_generic_to_shared(Bs);

    // ldmatrix per-lane base offsets (bytes)
    const int lmat = lane >> 3;         // 0..3
    const int lrr  = lane & 7;          // 0..7
    // A x4: mats = (row+0,k0),(row+8,k0),(row+0,k4),(row+8,k4)
    const uint32_t aoff = (uint32_t)(((wm0 + (lmat & 1)*8 + lrr)*SLD + (lmat >> 1)*4) * 4);
    // B x4 (two n8 blocks): mats = (n+0,k0),(n+0,k4),(n+8,k0),(n+8,k4)
    const uint32_t boff = (uint32_t)(((wn0 + (lmat >> 1)*8 + lrr)*SLD + (lmat & 1)*4) * 4);

    float acc[4][4][4];
    #pragma unroll
    for (int i = 0; i < 4; i++)
        #pragma unroll
        for (int j = 0; j < 4; j++)
            #pragma unroll
            for (int q = 0; q < 4; q++) acc[i][j][q] = 0.f;

    const float* agp = A + (size_t)(m0 + lrow)*K + lq0;
    const float* bgp = B + (size_t)(n0 + lrow)*K + lq0;

    auto load_stage = [&](int it, int st) {
        const int kc = it*32;
        uint32_t da = sAu + (uint32_t)((st*128*SLD + lrow*SLD + lq0) * 4);
        uint32_t db = sBu + (uint32_t)((st*128*SLD + lrow*SLD + lq0) * 4);
        #pragma unroll
        for (int q = 0; q < 4; q++) {
            cp16(da + q*16, agp + kc + q*4);
            cp16(db + q*16, bgp + kc + q*4);
        }
    };

    const int iters = K >> 5;
    load_stage(0, 0);
    asm volatile("cp.async.commit_group;\n" ::: "memory");
    load_stage(1, 1);
    asm volatile("cp.async.commit_group;\n" ::: "memory");

    for (int it = 0; it < iters; it++) {
        asm volatile("cp.async.wait_group 1;\n" ::: "memory");
        __syncthreads();

        const int st = it & 1;
        const uint32_t stA = sAu + (uint32_t)(st*128*SLD*4);
        const uint32_t stB = sBu + (uint32_t)(st*128*SLD*4);
        #pragma unroll
        for (int kb = 0; kb < 4; kb++) {
            const uint32_t kboff = (uint32_t)(kb*8*4);
            uint32_t af[4][4], bf[8];
            #pragma unroll
            for (int i = 0; i < 4; i++)
                ldsm4(af[i], stA + aoff + (uint32_t)(i*16*SLD*4) + kboff);
            ldsm4(bf,     stB + boff + kboff);
            ldsm4(bf + 4, stB + boff + (uint32_t)(16*SLD*4) + kboff);
            #pragma unroll
            for (int i = 0; i < 4; i++)
                #pragma unroll
                for (int j = 0; j < 4; j++)
                    mma_tf32(acc[i][j], af[i], bf + j*2);
        }
        __syncthreads();
        if (it + 2 < iters) load_stage(it + 2, st);
        asm volatile("cp.async.commit_group;\n" ::: "memory");
    }

    // ---- epilogue ----
    #pragma unroll
    for (int i = 0; i < 4; i++) {
        #pragma unroll
        for (int j = 0; j < 4; j++) {
            #pragma unroll
            for (int hh = 0; hh < 2; hh++) {
                const int row = m0 + wm0 + i*16 + g + hh*8;
                const int col = n0 + wn0 + j*8 + 2*cc;
                float vx = acc[i][j][hh*2 + 0];
                float vy = acc[i][j][hh*2 + 1];
                const size_t off = (size_t)row*N + col;
                if (EPMODE == 1) {
                    vx = 1.f/(1.f + __expf(-vx));
                    vy = 1.f/(1.f + __expf(-vy));
                } else if (EPMODE == 2) {
                    vx = fmaxf(vx, 0.f); vx = rtf(vx*vx);
                    vy = fmaxf(vy, 0.f); vy = rtf(vy*vy);
                } else if (EPMODE == 3) {
                    float2 c = *(const float2*)&C[off];
                    vx += c.x; vy += c.y;
                } else if (EPMODE == 4) {
                    float2 c = *(const float2*)&C[off];
                    float2 m = *(const float2*)&mulsrc[off];
                    vx = c.x + m.x*vx; vy = c.y + m.y*vy;
                }
                *(float2*)&C[off] = make_float2(vx, vy);
            }
        }
    }
}

// ------------------------------- WKV scan ----------------------------------
__global__ void wkv_pass1(const float* __restrict__ K, const float* __restrict__ V,
                          const float* __restrict__ td)
{
    int bc = blockIdx.x >> 2;
    int a  = (blockIdx.x & 3)*256 + threadIdx.x;
    int b  = bc / NCH, c = bc % NCH;
    float w_ = -__expf(td[a]);
    float aa = 0.f, bb = 0.f, pp = NEGv;
    const float* kp = K + ((size_t)(b*Td + c*CHUNK))*Ad + a;
    const float* vp = V + ((size_t)(b*Td + c*CHUNK))*Ad + a;
    #pragma unroll 4
    for (int t = 0; t < CHUNK; t++) {
        float kt = kp[(size_t)t*Ad], vt = vp[(size_t)t*Ad];
        float q2 = fmaxf(pp + w_, kt);
        float e1 = __expf(pp + w_ - q2), e2 = __expf(kt - q2);
        aa = e1*aa + e2*vt; bb = e1*bb + e2; pp = q2;
    }
    int idx = (b*NCH + c)*Ad + a;
    g_sa[idx] = aa; g_sb[idx] = bb; g_sp[idx] = pp;
}

__global__ void wkv_pass2(const float* __restrict__ td)
{
    int idx = blockIdx.x*256 + threadIdx.x;   // 0..4095
    int b = idx >> 10, a = idx & (Ad-1);
    float w_ = -__expf(td[a]);
    float wC = w_ * (float)CHUNK;
    float aa = 0.f, bb = 0.f, pp = NEGv;
    for (int c = 0; c < NCH; c++) {
        int i = (b*NCH + c)*Ad + a;
        g_ca[i] = aa; g_cb[i] = bb; g_cp[i] = pp;
        float p1 = pp + wC;
        float sa = g_sa[i], sb = g_sb[i], sp = g_sp[i];
        float q  = fmaxf(p1, sp);
        float e1 = __expf(p1 - q), e2 = __expf(sp - q);
        aa = aa*e1 + sa*e2; bb = bb*e1 + sb*e2; pp = q;
    }
}

// pass3 also multiplies by r and tf32-rounds (output feeds wo GEMM as A)
__global__ void wkv_pass3(const float* __restrict__ K, const float* __restrict__ V,
                          const float* __restrict__ R, float* __restrict__ Y,
                          const float* __restrict__ td, const float* __restrict__ tf)
{
    int bc = blockIdx.x >> 2;
    int a  = (blockIdx.x & 3)*256 + threadIdx.x;
    int b  = bc / NCH, c = bc % NCH;
    float w_ = -__expf(td[a]);
    float u_ = tf[a];
    int idx = (b*NCH + c)*Ad + a;
    float aa = g_ca[idx], bb = g_cb[idx], pp = g_cp[idx];
    size_t off0 = ((size_t)(b*Td + c*CHUNK))*Ad + a;
    #pragma unroll 4
    for (int t = 0; t < CHUNK; t++) {
        size_t off = off0 + (size_t)t*Ad;
        float kt = K[off], vt = V[off];
        float uk = u_ + kt;
        float q  = fmaxf(pp, uk);
        float e1 = __expf(uk - q), e2 = __expf(pp - q);
        float outv = (aa*e2 + e1*vt) / (bb*e2 + e1);
        Y[off] = rtf(R[off] * outv);
        float q2 = fmaxf(pp + w_, kt);
        float s1 = __expf(pp + w_ - q2), s2 = __expf(kt - q2);
        aa = s1*aa + s2*vt; bb = s1*bb + s2; pp = q2;
    }
}

// ------------------------------- driver ------------------------------------
extern "C" void kernel_launch(void* const* d_in, const int* in_sizes, int n_in,
                              void* d_out, int out_size)
{
    const int*   ids       = (const int*)  d_in[0];
    const float* embed     = (const float*)d_in[1];
    const float* pre_ln_w  = (const float*)d_in[2];
    const float* pre_ln_b  = (const float*)d_in[3];
    const float* post_ln_w = (const float*)d_in[4];
    const float* post_ln_b = (const float*)d_in[5];
    const float* ln1_w     = (const float*)d_in[6];
    const float* ln1_b     = (const float*)d_in[7];
    const float* ln2_w     = (const float*)d_in[8];
    const float* ln2_b     = (const float*)d_in[9];
    const float* mix_k     = (const float*)d_in[10];
    const float* mix_v     = (const float*)d_in[11];
    const float* mix_r     = (const float*)d_in[12];
    const float* att_wk    = (const float*)d_in[13];
    const float* att_wv    = (const float*)d_in[14];
    const float* att_wr    = (const float*)d_in[15];
    const float* att_wo    = (const float*)d_in[16];
    const float* time_decay= (const float*)d_in[17];
    const float* time_first= (const float*)d_in[18];
    const float* fmix_k    = (const float*)d_in[19];
    const float* fmix_r    = (const float*)d_in[20];
    const float* ffn_wk    = (const float*)d_in[21];
    const float* ffn_wr    = (const float*)d_in[22];
    const float* ffn_wv    = (const float*)d_in[23];

    float* out = (float*)d_out;

    float *h, *k, *v, *r, *y, *kk, *rr, *xk, *xv, *xr;
    float *cwk, *cwv, *cwr, *cwo, *cfwk, *cfwr, *cfwv;
    cudaGetSymbolAddress((void**)&h,  g_h);
    cudaGetSymbolAddress((void**)&k,  g_k);
    cudaGetSymbolAddress((void**)&v,  g_v);
    cudaGetSymbolAddress((void**)&r,  g_r);
    cudaGetSymbolAddress((void**)&y,  g_y);
    cudaGetSymbolAddress((void**)&kk, g_kk);
    cudaGetSymbolAddress((void**)&rr, g_rr);
    cudaGetSymbolAddress((void**)&xk, g_xk);
    cudaGetSymbolAddress((void**)&xv, g_xv);
    cudaGetSymbolAddress((void**)&xr, g_xr);
    cudaGetSymbolAddress((void**)&cwk,  g_cwk);
    cudaGetSymbolAddress((void**)&cwv,  g_cwv);
    cudaGetSymbolAddress((void**)&cwr,  g_cwr);
    cudaGetSymbolAddress((void**)&cwo,  g_cwo);
    cudaGetSymbolAddress((void**)&cfwk, g_cfwk);
    cudaGetSymbolAddress((void**)&cfwr, g_cfwr);
    cudaGetSymbolAddress((void**)&cfwv, g_cfwv);

    static bool attr_done = false;
    if (!attr_done) {
        cudaFuncSetAttribute(gemm_tc<0>, cudaFuncAttributeMaxDynamicSharedMemorySize, SMEM_BYTES);
        cudaFuncSetAttribute(gemm_tc<1>, cudaFuncAttributeMaxDynamicSharedMemorySize, SMEM_BYTES);
        cudaFuncSetAttribute(gemm_tc<2>, cudaFuncAttributeMaxDynamicSharedMemorySize, SMEM_BYTES);
        cudaFuncSetAttribute(gemm_tc<3>, cudaFuncAttributeMaxDynamicSharedMemorySize, SMEM_BYTES);
        cudaFuncSetAttribute(gemm_tc<4>, cudaFuncAttributeMaxDynamicSharedMemorySize, SMEM_BYTES);
        attr_done = true;
    }

    dim3 t256(256);
    dim3 gH(Hd/128, Mdim/128);      // N=1024
    dim3 gI(Id/128, Mdim/128);      // N=4096

    // weight pre-rounding
    {
        const int TPB = 256;
        size_t n4;
        n4 = (size_t)Ld*Ad*Hd/4;
        round_tf32<<<(unsigned)((n4+TPB-1)/TPB), TPB>>>(att_wk, cwk, n4);
        round_tf32<<<(unsigned)((n4+TPB-1)/TPB), TPB>>>(att_wv, cwv, n4);
        round_tf32<<<(unsigned)((n4+TPB-1)/TPB), TPB>>>(att_wr, cwr, n4);
        round_tf32<<<(unsigned)((n4+TPB-1)/TPB), TPB>>>(att_wo, cwo, n4);
        n4 = (size_t)Ld*Id*Hd/4;
        round_tf32<<<(unsigned)((n4+TPB-1)/TPB), TPB>>>(ffn_wk, cfwk, n4);
        round_tf32<<<(unsigned)((n4+TPB-1)/TPB), TPB>>>(ffn_wv, cfwv, n4);
        n4 = (size_t)Ld*Hd*Hd/4;
        round_tf32<<<(unsigned)((n4+TPB-1)/TPB), TPB>>>(ffn_wr, cfwr, n4);
    }

    embed_ln_kernel<<<Mdim, t256>>>(ids, embed, pre_ln_w, pre_ln_b, h);

    for (int i = 0; i < Ld; i++) {
        const float* td = time_decay + (size_t)i*Ad;
        const float* tf = time_first + (size_t)i*Ad;

        ln_mix3<<<Mdim, t256>>>(h, ln1_w + (size_t)i*Hd, ln1_b + (size_t)i*Hd,
                                mix_k + (size_t)i*Hd, mix_v + (size_t)i*Hd,
                                mix_r + (size_t)i*Hd, xk, xv, xr);

        gemm_tc<0><<<gH, t256, SMEM_BYTES>>>(xk, cwk + (size_t)i*Ad*Hd, k, nullptr, Mdim, Ad, Hd);
        gemm_tc<0><<<gH, t256, SMEM_BYTES>>>(xv, cwv + (size_t)i*Ad*Hd, v, nullptr, Mdim, Ad, Hd);
        gemm_tc<1><<<gH, t256, SMEM_BYTES>>>(xr, cwr + (size_t)i*Ad*Hd, r, nullptr, Mdim, Ad, Hd);

        wkv_pass1<<<Bd*NCH*4, t256>>>(k, v, td);
        wkv_pass2<<<16, t256>>>(td);
        wkv_pass3<<<Bd*NCH*4, t256>>>(k, v, r, y, td, tf);

        // h += (r*y) @ wo^T   (y already holds tf32(r*y))
        gemm_tc<3><<<gH, t256, SMEM_BYTES>>>(y, cwo + (size_t)i*Hd*Ad, h, nullptr, Mdim, Hd, Ad);

        ln_mix2<<<Mdim, t256>>>(h, ln2_w + (size_t)i*Hd, ln2_b + (size_t)i*Hd,
                                fmix_k + (size_t)i*Hd, fmix_r + (size_t)i*Hd, xk, xr);

        gemm_tc<2><<<gI, t256, SMEM_BYTES>>>(xk, cfwk + (size_t)i*Id*Hd, kk, nullptr, Mdim, Id, Hd);
        gemm_tc<1><<<gH, t256, SMEM_BYTES>>>(xr, cfwr + (size_t)i*Hd*Hd, rr, nullptr, Mdim, Hd, Hd);
        gemm_tc<4><<<gH, t256, SMEM_BYTES>>>(kk, cfwv + (size_t)i*Hd*Id, h, rr, Mdim, Hd, Id);
    }

    ln_kernel<<<Mdim, t256>>>(h, post_ln_w, post_ln_b, out);
}

// round 7
// speedup vs baseline: 2.6806x; 1.0296x over previous
#include <cuda_runtime.h>
#include <cstdint>

// ---------------------------------------------------------------------------
// RWKV forward: L=6, H=1024, A=1024, I=4096, B=4, T=2048, fp32
// Round 7: 3-stage cp.async single-sync pipeline; merged weight rounding
// (one launch, so ncu -s5 lands on a GEMM). TF32 mma.sync + ldmatrix.
// ---------------------------------------------------------------------------

#define Ld 6
#define Hd 1024
#define Ad 1024
#define Id 4096
#define Bd 4
#define Td 2048
#define Mdim (Bd*Td)          // 8192 tokens
#define EPSv 1e-5f
#define NEGv -1e38f

#define CHUNK 64
#define NCH (Td/CHUNK)        // 32

#define SLD 36                // smem row stride (floats), conflict-free frags
#define NSTG 3
#define SMEM_BYTES (NSTG*2*128*SLD*4)   // 3 stages x (A+B) x 128 x SLD floats

// ------------------------- scratch (static, no allocs) ---------------------
__device__ float g_h [Mdim*Hd];
__device__ float g_k [Mdim*Ad];
__device__ float g_v [Mdim*Ad];
__device__ float g_r [Mdim*Ad];
__device__ float g_y [Mdim*Ad];
__device__ float g_kk[(size_t)Mdim*Id];
__device__ float g_rr[Mdim*Hd];
__device__ float g_xk[Mdim*Hd];
__device__ float g_xv[Mdim*Hd];
__device__ float g_xr[Mdim*Hd];

// tf32-rounded weight copies
__device__ float g_cwk [Ld*Ad*Hd];
__device__ float g_cwv [Ld*Ad*Hd];
__device__ float g_cwr [Ld*Ad*Hd];
__device__ float g_cwo [Ld*Hd*Ad];
__device__ float g_cfwk[(size_t)Ld*Id*Hd];
__device__ float g_cfwr[Ld*Hd*Hd];
__device__ float g_cfwv[(size_t)Ld*Hd*Id];

__device__ float g_sa[Bd*NCH*Ad], g_sb[Bd*NCH*Ad], g_sp[Bd*NCH*Ad];
__device__ float g_ca[Bd*NCH*Ad], g_cb[Bd*NCH*Ad], g_cp[Bd*NCH*Ad];

// ------------------------------ helpers -------------------------------------
__device__ __forceinline__ uint32_t f2tf(float f)
{
    uint32_t u;
    asm("cvt.rna.tf32.f32 %0, %1;" : "=r"(u) : "f"(f));
    return u;
}
__device__ __forceinline__ float rtf(float f) { return __uint_as_float(f2tf(f)); }

__device__ __forceinline__ void mma_tf32(float* c, const uint32_t* a, const uint32_t* b)
{
    asm volatile(
        "mma.sync.aligned.m16n8k8.row.col.f32.tf32.tf32.f32 "
        "{%0,%1,%2,%3}, {%4,%5,%6,%7}, {%8,%9}, {%0,%1,%2,%3};"
        : "+f"(c[0]), "+f"(c[1]), "+f"(c[2]), "+f"(c[3])
        : "r"(a[0]), "r"(a[1]), "r"(a[2]), "r"(a[3]),
          "r"(b[0]), "r"(b[1]));
}

__device__ __forceinline__ void cp16(uint32_t dst, const void* src)
{
    asm volatile("cp.async.cg.shared.global [%0], [%1], 16;\n"
                 :: "r"(dst), "l"(src));
}

__device__ __forceinline__ void ldsm4(uint32_t* r, uint32_t addr)
{
    asm volatile("ldmatrix.sync.aligned.m8n8.x4.shared.b16 {%0,%1,%2,%3}, [%4];"
                 : "=r"(r[0]), "=r"(r[1]), "=r"(r[2]), "=r"(r[3])
                 : "r"(addr));
}

// ---------------- merged weight tf32 pre-rounding (ONE launch) --------------
#define S_AH (Ld*Ad*Hd/4)          // 1,572,864 f4  (wk/wv/wr/wo each)
#define S_IH ((size_t)Ld*Id*Hd/4)  // 6,291,456 f4  (fwk / fwv each)
#define S_HH (Ld*Hd*Hd/4)          // 1,572,864 f4  (fwr)
#define TOT4 (4*(size_t)S_AH + 2*S_IH + (size_t)S_HH)   // 20,447,232

__global__ void round_all(const float* wk, const float* wv, const float* wr,
                          const float* wo, const float* fwk, const float* fwr,
                          const float* fwv,
                          float* cwk, float* cwv, float* cwr, float* cwo,
                          float* cfwk, float* cfwr, float* cfwv)
{
    size_t i = (size_t)blockIdx.x*blockDim.x + threadIdx.x;
    if (i >= TOT4) return;
    const float* src; float* dst; size_t off;
    if (i < 4*(size_t)S_AH) {
        size_t seg = i / S_AH; off = i % S_AH;
        src = (seg==0)?wk:(seg==1)?wv:(seg==2)?wr:wo;
        dst = (seg==0)?cwk:(seg==1)?cwv:(seg==2)?cwr:cwo;
    } else if (i < 4*(size_t)S_AH + S_IH) {
        off = i - 4*(size_t)S_AH; src = fwk; dst = cfwk;
    } else if (i < 4*(size_t)S_AH + S_IH + (size_t)S_HH) {
        off = i - 4*(size_t)S_AH - S_IH; src = fwr; dst = cfwr;
    } else {
        off = i - 4*(size_t)S_AH - S_IH - (size_t)S_HH; src = fwv; dst = cfwv;
    }
    float4 v = ((const float4*)src)[off];
    v.x = rtf(v.x); v.y = rtf(v.y); v.z = rtf(v.z); v.w = rtf(v.w);
    ((float4*)dst)[off] = v;
}

// ----------------------------- reductions -----------------------------------
__device__ __forceinline__ void block_reduce4(float& a, float& b, float& c, float& d)
{
    #pragma unroll
    for (int o = 16; o > 0; o >>= 1) {
        a += __shfl_xor_sync(0xffffffffu, a, o);
        b += __shfl_xor_sync(0xffffffffu, b, o);
        c += __shfl_xor_sync(0xffffffffu, c, o);
        d += __shfl_xor_sync(0xffffffffu, d, o);
    }
    __shared__ float sh[4][8];
    int w = threadIdx.x >> 5, l = threadIdx.x & 31;
    if (l == 0) { sh[0][w] = a; sh[1][w] = b; sh[2][w] = c; sh[3][w] = d; }
    __syncthreads();
    if (w == 0) {
        a = (l < 8) ? sh[0][l] : 0.f;
        b = (l < 8) ? sh[1][l] : 0.f;
        c = (l < 8) ? sh[2][l] : 0.f;
        d = (l < 8) ? sh[3][l] : 0.f;
        #pragma unroll
        for (int o = 4; o > 0; o >>= 1) {
            a += __shfl_xor_sync(0xffffffffu, a, o);
            b += __shfl_xor_sync(0xffffffffu, b, o);
            c += __shfl_xor_sync(0xffffffffu, c, o);
            d += __shfl_xor_sync(0xffffffffu, d, o);
        }
        if (l == 0) { sh[0][0] = a; sh[1][0] = b; sh[2][0] = c; sh[3][0] = d; }
    }
    __syncthreads();
    a = sh[0][0]; b = sh[1][0]; c = sh[2][0]; d = sh[3][0];
}

// plain LN (final)
__global__ void ln_kernel(const float* __restrict__ in,
                          const float* __restrict__ w,
                          const float* __restrict__ b,
                          float* __restrict__ out)
{
    size_t row = blockIdx.x;
    const float4 v = ((const float4*)(in + row*Hd))[threadIdx.x];
    float s  = v.x + v.y + v.z + v.w;
    float s2 = v.x*v.x + v.y*v.y + v.z*v.z + v.w*v.w;
    float z0 = 0.f, z1 = 0.f;
    block_reduce4(s, s2, z0, z1);
    float mu  = s * (1.f/Hd);
    float inv = rsqrtf(s2*(1.f/Hd) - mu*mu + EPSv);
    float4 wv = ((const float4*)w)[threadIdx.x];
    float4 bv = ((const float4*)b)[threadIdx.x];
    float4 o;
    o.x = (v.x - mu)*inv*wv.x + bv.x;
    o.y = (v.y - mu)*inv*wv.y + bv.y;
    o.z = (v.z - mu)*inv*wv.z + bv.z;
    o.w = (v.w - mu)*inv*wv.w + bv.w;
    ((float4*)(out + row*Hd))[threadIdx.x] = o;
}

__global__ void embed_ln_kernel(const int* __restrict__ ids,
                                const float* __restrict__ embed,
                                const float* __restrict__ w,
                                const float* __restrict__ b,
                                float* __restrict__ out)
{
    size_t row = blockIdx.x;
    size_t id  = (size_t)ids[row];
    const float4 v = ((const float4*)(embed + id*Hd))[threadIdx.x];
    float s  = v.x + v.y + v.z + v.w;
    float s2 = v.x*v.x + v.y*v.y + v.z*v.z + v.w*v.w;
    float z0 = 0.f, z1 = 0.f;
    block_reduce4(s, s2, z0, z1);
    float mu  = s * (1.f/Hd);
    float inv = rsqrtf(s2*(1.f/Hd) - mu*mu + EPSv);
    float4 wv = ((const float4*)w)[threadIdx.x];
    float4 bv = ((const float4*)b)[threadIdx.x];
    float4 o;
    o.x = (v.x - mu)*inv*wv.x + bv.x;
    o.y = (v.y - mu)*inv*wv.y + bv.y;
    o.z = (v.z - mu)*inv*wv.z + bv.z;
    o.w = (v.w - mu)*inv*wv.w + bv.w;
    ((float4*)(out + row*Hd))[threadIdx.x] = o;
}

// fused LN + time-mix (3 outputs, att) — writes tf32-rounded mixes
__global__ void ln_mix3(const float* __restrict__ hsrc,
                        const float* __restrict__ lw, const float* __restrict__ lb,
                        const float* __restrict__ mk, const float* __restrict__ mv,
                        const float* __restrict__ mr,
                        float* __restrict__ xk, float* __restrict__ xv,
                        float* __restrict__ xr)
{
    size_t row = blockIdx.x;
    int t = threadIdx.x;
    bool hp = (row & (Td-1)) != 0;
    float4 cur = ((const float4*)(hsrc + row*Hd))[t];
    float4 prv = make_float4(0.f,0.f,0.f,0.f);
    if (hp) prv = ((const float4*)(hsrc + (row-1)*Hd))[t];
    float s1 = cur.x+cur.y+cur.z+cur.w;
    float q1 = cur.x*cur.x+cur.y*cur.y+cur.z*cur.z+cur.w*cur.w;
    float s2 = prv.x+prv.y+prv.z+prv.w;
    float q2 = prv.x*prv.x+prv.y*prv.y+prv.z*prv.z+prv.w*prv.w;
    block_reduce4(s1, q1, s2, q2);
    float mu1 = s1*(1.f/Hd), inv1 = rsqrtf(q1*(1.f/Hd) - mu1*mu1 + EPSv);
    float mu2 = s2*(1.f/Hd), inv2 = rsqrtf(q2*(1.f/Hd) - mu2*mu2 + EPSv);
    float4 wv = ((const float4*)lw)[t];
    float4 bv = ((const float4*)lb)[t];
    float4 xc, xp;
    xc.x = (cur.x-mu1)*inv1*wv.x + bv.x;  xc.y = (cur.y-mu1)*inv1*wv.y + bv.y;
    xc.z = (cur.z-mu1)*inv1*wv.z + bv.z;  xc.w = (cur.w-mu1)*inv1*wv.w + bv.w;
    if (hp) {
        xp.x = (prv.x-mu2)*inv2*wv.x + bv.x;  xp.y = (prv.y-mu2)*inv2*wv.y + bv.y;
        xp.z = (prv.z-mu2)*inv2*wv.z + bv.z;  xp.w = (prv.w-mu2)*inv2*wv.w + bv.w;
    } else xp = make_float4(0.f,0.f,0.f,0.f);

    float4 m, o;
    m = ((const float4*)mk)[t];
    o.x = rtf(m.x*xc.x + (1.f-m.x)*xp.x); o.y = rtf(m.y*xc.y + (1.f-m.y)*xp.y);
    o.z = rtf(m.z*xc.z + (1.f-m.z)*xp.z); o.w = rtf(m.w*xc.w + (1.f-m.w)*xp.w);
    ((float4*)(xk + row*Hd))[t] = o;
    m = ((const float4*)mv)[t];
    o.x = rtf(m.x*xc.x + (1.f-m.x)*xp.x); o.y = rtf(m.y*xc.y + (1.f-m.y)*xp.y);
    o.z = rtf(m.z*xc.z + (1.f-m.z)*xp.z); o.w = rtf(m.w*xc.w + (1.f-m.w)*xp.w);
    ((float4*)(xv + row*Hd))[t] = o;
    m = ((const float4*)mr)[t];
    o.x = rtf(m.x*xc.x + (1.f-m.x)*xp.x); o.y = rtf(m.y*xc.y + (1.f-m.y)*xp.y);
    o.z = rtf(m.z*xc.z + (1.f-m.z)*xp.z); o.w = rtf(m.w*xc.w + (1.f-m.w)*xp.w);
    ((float4*)(xr + row*Hd))[t] = o;
}

// fused LN + channel-mix (2 outputs, ffn)
__global__ void ln_mix2(const float* __restrict__ hsrc,
                        const float* __restrict__ lw, const float* __restrict__ lb,
                        const float* __restrict__ mk, const float* __restrict__ mr,
                        float* __restrict__ xk, float* __restrict__ xr)
{
    size_t row = blockIdx.x;
    int t = threadIdx.x;
    bool hp = (row & (Td-1)) != 0;
    float4 cur = ((const float4*)(hsrc + row*Hd))[t];
    float4 prv = make_float4(0.f,0.f,0.f,0.f);
    if (hp) prv = ((const float4*)(hsrc + (row-1)*Hd))[t];
    float s1 = cur.x+cur.y+cur.z+cur.w;
    float q1 = cur.x*cur.x+cur.y*cur.y+cur.z*cur.z+cur.w*cur.w;
    float s2 = prv.x+prv.y+prv.z+prv.w;
    float q2 = prv.x*prv.x+prv.y*prv.y+prv.z*prv.z+prv.w*prv.w;
    block_reduce4(s1, q1, s2, q2);
    float mu1 = s1*(1.f/Hd), inv1 = rsqrtf(q1*(1.f/Hd) - mu1*mu1 + EPSv);
    float mu2 = s2*(1.f/Hd), inv2 = rsqrtf(q2*(1.f/Hd) - mu2*mu2 + EPSv);
    float4 wv = ((const float4*)lw)[t];
    float4 bv = ((const float4*)lb)[t];
    float4 xc, xp;
    xc.x = (cur.x-mu1)*inv1*wv.x + bv.x;  xc.y = (cur.y-mu1)*inv1*wv.y + bv.y;
    xc.z = (cur.z-mu1)*inv1*wv.z + bv.z;  xc.w = (cur.w-mu1)*inv1*wv.w + bv.w;
    if (hp) {
        xp.x = (prv.x-mu2)*inv2*wv.x + bv.x;  xp.y = (prv.y-mu2)*inv2*wv.y + bv.y;
        xp.z = (prv.z-mu2)*inv2*wv.z + bv.z;  xp.w = (prv.w-mu2)*inv2*wv.w + bv.w;
    } else xp = make_float4(0.f,0.f,0.f,0.f);

    float4 m, o;
    m = ((const float4*)mk)[t];
    o.x = rtf(m.x*xc.x + (1.f-m.x)*xp.x); o.y = rtf(m.y*xc.y + (1.f-m.y)*xp.y);
    o.z = rtf(m.z*xc.z + (1.f-m.z)*xp.z); o.w = rtf(m.w*xc.w + (1.f-m.w)*xp.w);
    ((float4*)(xk + row*Hd))[t] = o;
    m = ((const float4*)mr)[t];
    o.x = rtf(m.x*xc.x + (1.f-m.x)*xp.x); o.y = rtf(m.y*xc.y + (1.f-m.y)*xp.y);
    o.z = rtf(m.z*xc.z + (1.f-m.z)*xp.z); o.w = rtf(m.w*xc.w + (1.f-m.w)*xp.w);
    ((float4*)(xr + row*Hd))[t] = o;
}

// ------------------------------ TF32 GEMM -----------------------------------
// C[m,n] = epi( sum_k A[m,k]*B[n,k] ); A,B pre-rounded to tf32 values.
// EPMODE: 0 store, 1 sigmoid, 2 tf32(relu^2), 3 C+=acc, 4 C = C + mulsrc*acc
// CTA 128x128, BK=32, warp tile 64x32, 8 warps, ldmatrix, 3-stage 1-sync.
template<int EPMODE>
__global__ __launch_bounds__(256, 2)
void gemm_tc(const float* __restrict__ A, const float* __restrict__ B,
             float* __restrict__ C, const float* __restrict__ mulsrc,
             int M, int N, int K)
{
    extern __shared__ float smem[];
    float* As = smem;                      // [NSTG][128*SLD]
    float* Bs = smem + NSTG*128*SLD;

    const int m0 = blockIdx.y * 128;
    const int n0 = blockIdx.x * 128;
    const int tid  = threadIdx.x;
    const int lane = tid & 31;
    const int wid  = tid >> 5;
    const int g  = lane >> 2;
    const int cc = lane & 3;
    const int wm0 = (wid >> 2) * 64;
    const int wn0 = (wid & 3) * 32;
    const int lrow = tid >> 1;          // 0..127
    const int lq0  = (tid & 1) * 16;    // float offset within 32-float row

    const uint32_t sAu = (uint32_t)__cvta_generic_to_shared(As);
    const uint32_t sBu = (uint32_t)__cvta_generic_to_shared(Bs);

    // ldmatrix per-lane base offsets (bytes)
    const int lmat = lane >> 3;         // 0..3
    const int lrr  = lane & 7;          // 0..7
    // A x4: mats = (row+0,k0),(row+8,k0),(row+0,k4),(row+8,k4)
    const uint32_t aoff = (uint32_t)(((wm0 + (lmat & 1)*8 + lrr)*SLD + (lmat >> 1)*4) * 4);
    // B x4 (two n8 blocks): mats = (n+0,k0),(n+0,k4),(n+8,k0),(n+8,k4)
    const uint32_t boff = (uint32_t)(((wn0 + (lmat >> 1)*8 + lrr)*SLD + (lmat & 1)*4) * 4);

    float acc[4][4][4];
    #pragma unroll
    for (int i = 0; i < 4; i++)
        #pragma unroll
        for (int j = 0; j < 4; j++)
            #pragma unroll
            for (int q = 0; q < 4; q++) acc[i][j][q] = 0.f;

    const float* agp = A + (size_t)(m0 + lrow)*K + lq0;
    const float* bgp = B + (size_t)(n0 + lrow)*K + lq0;

    auto load_stage = [&](int it, int st) {
        const int kc = it*32;
        uint32_t da = sAu + (uint32_t)((st*128*SLD + lrow*SLD + lq0) * 4);
        uint32_t db = sBu + (uint32_t)((st*128*SLD + lrow*SLD + lq0) * 4);
        #pragma unroll
        for (int q = 0; q < 4; q++) {
            cp16(da + q*16, agp + kc + q*4);
            cp16(db + q*16, bgp + kc + q*4);
        }
    };

    const int iters = K >> 5;
    load_stage(0, 0);
    asm volatile("cp.async.commit_group;\n" ::: "memory");
    load_stage(1, 1);
    asm volatile("cp.async.commit_group;\n" ::: "memory");

    for (int it = 0; it < iters; it++) {
        asm volatile("cp.async.wait_group 1;\n" ::: "memory");
        __syncthreads();

        // refill slot (it+2)%3 (freed by all warps at iteration it-1)
        if (it + 2 < iters) load_stage(it + 2, (it + 2) % NSTG);
        asm volatile("cp.async.commit_group;\n" ::: "memory");

        const int st = it % NSTG;
        const uint32_t stA = sAu + (uint32_t)(st*128*SLD*4);
        const uint32_t stB = sBu + (uint32_t)(st*128*SLD*4);
        #pragma unroll
        for (int kb = 0; kb < 4; kb++) {
            const uint32_t kboff = (uint32_t)(kb*8*4);
            uint32_t af[4][4], bf[8];
            #pragma unroll
            for (int i = 0; i < 4; i++)
                ldsm4(af[i], stA + aoff + (uint32_t)(i*16*SLD*4) + kboff);
            ldsm4(bf,     stB + boff + kboff);
            ldsm4(bf + 4, stB + boff + (uint32_t)(16*SLD*4) + kboff);
            #pragma unroll
            for (int i = 0; i < 4; i++)
                #pragma unroll
                for (int j = 0; j < 4; j++)
                    mma_tf32(acc[i][j], af[i], bf + j*2);
        }
    }

    // ---- epilogue ----
    #pragma unroll
    for (int i = 0; i < 4; i++) {
        #pragma unroll
        for (int j = 0; j < 4; j++) {
            #pragma unroll
            for (int hh = 0; hh < 2; hh++) {
                const int row = m0 + wm0 + i*16 + g + hh*8;
                const int col = n0 + wn0 + j*8 + 2*cc;
                float vx = acc[i][j][hh*2 + 0];
                float vy = acc[i][j][hh*2 + 1];
                const size_t off = (size_t)row*N + col;
                if (EPMODE == 1) {
                    vx = 1.f/(1.f + __expf(-vx));
                    vy = 1.f/(1.f + __expf(-vy));
                } else if (EPMODE == 2) {
                    vx = fmaxf(vx, 0.f); vx = rtf(vx*vx);
                    vy = fmaxf(vy, 0.f); vy = rtf(vy*vy);
                } else if (EPMODE == 3) {
                    float2 c = *(const float2*)&C[off];
                    vx += c.x; vy += c.y;
                } else if (EPMODE == 4) {
                    float2 c = *(const float2*)&C[off];
                    float2 m = *(const float2*)&mulsrc[off];
                    vx = c.x + m.x*vx; vy = c.y + m.y*vy;
                }
                *(float2*)&C[off] = make_float2(vx, vy);
            }
        }
    }
}

// ------------------------------- WKV scan ----------------------------------
__global__ void wkv_pass1(const float* __restrict__ K, const float* __restrict__ V,
                          const float* __restrict__ td)
{
    int bc = blockIdx.x >> 2;
    int a  = (blockIdx.x & 3)*256 + threadIdx.x;
    int b  = bc / NCH, c = bc % NCH;
    float w_ = -__expf(td[a]);
    float aa = 0.f, bb = 0.f, pp = NEGv;
    const float* kp = K + ((size_t)(b*Td + c*CHUNK))*Ad + a;
    const float* vp = V + ((size_t)(b*Td + c*CHUNK))*Ad + a;
    #pragma unroll 4
    for (int t = 0; t < CHUNK; t++) {
        float kt = kp[(size_t)t*Ad], vt = vp[(size_t)t*Ad];
        float q2 = fmaxf(pp + w_, kt);
        float e1 = __expf(pp + w_ - q2), e2 = __expf(kt - q2);
        aa = e1*aa + e2*vt; bb = e1*bb + e2; pp = q2;
    }
    int idx = (b*NCH + c)*Ad + a;
    g_sa[idx] = aa; g_sb[idx] = bb; g_sp[idx] = pp;
}

__global__ void wkv_pass2(const float* __restrict__ td)
{
    int idx = blockIdx.x*256 + threadIdx.x;   // 0..4095
    int b = idx >> 10, a = idx & (Ad-1);
    float w_ = -__expf(td[a]);
    float wC = w_ * (float)CHUNK;
    float aa = 0.f, bb = 0.f, pp = NEGv;
    for (int c = 0; c < NCH; c++) {
        int i = (b*NCH + c)*Ad + a;
        g_ca[i] = aa; g_cb[i] = bb; g_cp[i] = pp;
        float p1 = pp + wC;
        float sa = g_sa[i], sb = g_sb[i], sp = g_sp[i];
        float q  = fmaxf(p1, sp);
        float e1 = __expf(p1 - q), e2 = __expf(sp - q);
        aa = aa*e1 + sa*e2; bb = bb*e1 + sb*e2; pp = q;
    }
}

// pass3 also multiplies by r and tf32-rounds (output feeds wo GEMM as A)
__global__ void wkv_pass3(const float* __restrict__ K, const float* __restrict__ V,
                          const float* __restrict__ R, float* __restrict__ Y,
                          const float* __restrict__ td, const float* __restrict__ tf)
{
    int bc = blockIdx.x >> 2;
    int a  = (blockIdx.x & 3)*256 + threadIdx.x;
    int b  = bc / NCH, c = bc % NCH;
    float w_ = -__expf(td[a]);
    float u_ = tf[a];
    int idx = (b*NCH + c)*Ad + a;
    float aa = g_ca[idx], bb = g_cb[idx], pp = g_cp[idx];
    size_t off0 = ((size_t)(b*Td + c*CHUNK))*Ad + a;
    #pragma unroll 4
    for (int t = 0; t < CHUNK; t++) {
        size_t off = off0 + (size_t)t*Ad;
        float kt = K[off], vt = V[off];
        float uk = u_ + kt;
        float q  = fmaxf(pp, uk);
        float e1 = __expf(uk - q), e2 = __expf(pp - q);
        float outv = (aa*e2 + e1*vt) / (bb*e2 + e1);
        Y[off] = rtf(R[off] * outv);
        float q2 = fmaxf(pp + w_, kt);
        float s1 = __expf(pp + w_ - q2), s2 = __expf(kt - q2);
        aa = s1*aa + s2*vt; bb = s1*bb + s2; pp = q2;
    }
}

// ------------------------------- driver ------------------------------------
extern "C" void kernel_launch(void* const* d_in, const int* in_sizes, int n_in,
                              void* d_out, int out_size)
{
    const int*   ids       = (const int*)  d_in[0];
    const float* embed     = (const float*)d_in[1];
    const float* pre_ln_w  = (const float*)d_in[2];
    const float* pre_ln_b  = (const float*)d_in[3];
    const float* post_ln_w = (const float*)d_in[4];
    const float* post_ln_b = (const float*)d_in[5];
    const float* ln1_w     = (const float*)d_in[6];
    const float* ln1_b     = (const float*)d_in[7];
    const float* ln2_w     = (const float*)d_in[8];
    const float* ln2_b     = (const float*)d_in[9];
    const float* mix_k     = (const float*)d_in[10];
    const float* mix_v     = (const float*)d_in[11];
    const float* mix_r     = (const float*)d_in[12];
    const float* att_wk    = (const float*)d_in[13];
    const float* att_wv    = (const float*)d_in[14];
    const float* att_wr    = (const float*)d_in[15];
    const float* att_wo    = (const float*)d_in[16];
    const float* time_decay= (const float*)d_in[17];
    const float* time_first= (const float*)d_in[18];
    const float* fmix_k    = (const float*)d_in[19];
    const float* fmix_r    = (const float*)d_in[20];
    const float* ffn_wk    = (const float*)d_in[21];
    const float* ffn_wr    = (const float*)d_in[22];
    const float* ffn_wv    = (const float*)d_in[23];

    float* out = (float*)d_out;

    float *h, *k, *v, *r, *y, *kk, *rr, *xk, *xv, *xr;
    float *cwk, *cwv, *cwr, *cwo, *cfwk, *cfwr, *cfwv;
    cudaGetSymbolAddress((void**)&h,  g_h);
    cudaGetSymbolAddress((void**)&k,  g_k);
    cudaGetSymbolAddress((void**)&v,  g_v);
    cudaGetSymbolAddress((void**)&r,  g_r);
    cudaGetSymbolAddress((void**)&y,  g_y);
    cudaGetSymbolAddress((void**)&kk, g_kk);
    cudaGetSymbolAddress((void**)&rr, g_rr);
    cudaGetSymbolAddress((void**)&xk, g_xk);
    cudaGetSymbolAddress((void**)&xv, g_xv);
    cudaGetSymbolAddress((void**)&xr, g_xr);
    cudaGetSymbolAddress((void**)&cwk,  g_cwk);
    cudaGetSymbolAddress((void**)&cwv,  g_cwv);
    cudaGetSymbolAddress((void**)&cwr,  g_cwr);
    cudaGetSymbolAddress((void**)&cwo,  g_cwo);
    cudaGetSymbolAddress((void**)&cfwk, g_cfwk);
    cudaGetSymbolAddress((void**)&cfwr, g_cfwr);
    cudaGetSymbolAddress((void**)&cfwv, g_cfwv);

    static bool attr_done = false;
    if (!attr_done) {
        cudaFuncSetAttribute(gemm_tc<0>, cudaFuncAttributeMaxDynamicSharedMemorySize, SMEM_BYTES);
        cudaFuncSetAttribute(gemm_tc<1>, cudaFuncAttributeMaxDynamicSharedMemorySize, SMEM_BYTES);
        cudaFuncSetAttribute(gemm_tc<2>, cudaFuncAttributeMaxDynamicSharedMemorySize, SMEM_BYTES);
        cudaFuncSetAttribute(gemm_tc<3>, cudaFuncAttributeMaxDynamicSharedMemorySize, SMEM_BYTES);
        cudaFuncSetAttribute(gemm_tc<4>, cudaFuncAttributeMaxDynamicSharedMemorySize, SMEM_BYTES);
        attr_done = true;
    }

    dim3 t256(256);
    dim3 gH(Hd/128, Mdim/128);      // N=1024
    dim3 gI(Id/128, Mdim/128);      // N=4096

    // weight pre-rounding — ONE launch (ncu -s5 then lands on a GEMM)
    {
        unsigned nb = (unsigned)((TOT4 + 255) / 256);
        round_all<<<nb, t256>>>(att_wk, att_wv, att_wr, att_wo,
                                ffn_wk, ffn_wr, ffn_wv,
                                cwk, cwv, cwr, cwo, cfwk, cfwr, cfwv);
    }

    embed_ln_kernel<<<Mdim, t256>>>(ids, embed, pre_ln_w, pre_ln_b, h);

    for (int i = 0; i < Ld; i++) {
        const float* td = time_decay + (size_t)i*Ad;
        const float* tf = time_first + (size_t)i*Ad;

        ln_mix3<<<Mdim, t256>>>(h, ln1_w + (size_t)i*Hd, ln1_b + (size_t)i*Hd,
                                mix_k + (size_t)i*Hd, mix_v + (size_t)i*Hd,
                                mix_r + (size_t)i*Hd, xk, xv, xr);

        gemm_tc<0><<<gH, t256, SMEM_BYTES>>>(xk, cwk + (size_t)i*Ad*Hd, k, nullptr, Mdim, Ad, Hd);
        gemm_tc<0><<<gH, t256, SMEM_BYTES>>>(xv, cwv + (size_t)i*Ad*Hd, v, nullptr, Mdim, Ad, Hd);
        gemm_tc<1><<<gH, t256, SMEM_BYTES>>>(xr, cwr + (size_t)i*Ad*Hd, r, nullptr, Mdim, Ad, Hd);

        wkv_pass1<<<Bd*NCH*4, t256>>>(k, v, td);
        wkv_pass2<<<16, t256>>>(td);
        wkv_pass3<<<Bd*NCH*4, t256>>>(k, v, r, y, td, tf);

        // h += (r*y) @ wo^T   (y already holds tf32(r*y))
        gemm_tc<3><<<gH, t256, SMEM_BYTES>>>(y, cwo + (size_t)i*Hd*Ad, h, nullptr, Mdim, Hd, Ad);

        ln_mix2<<<Mdim, t256>>>(h, ln2_w + (size_t)i*Hd, ln2_b + (size_t)i*Hd,
                                fmix_k + (size_t)i*Hd, fmix_r + (size_t)i*Hd, xk, xr);

        gemm_tc<2><<<gI, t256, SMEM_BYTES>>>(xk, cfwk + (size_t)i*Id*Hd, kk, nullptr, Mdim, Id, Hd);
        gemm_tc<1><<<gH, t256, SMEM_BYTES>>>(xr, cfwr + (size_t)i*Hd*Hd, rr, nullptr, Mdim, Hd, Hd);
        gemm_tc<4><<<gH, t256, SMEM_BYTES>>>(kk, cfwv + (size_t)i*Hd*Id, h, rr, Mdim, Hd, Id);
    }

    ln_kernel<<<Mdim, t256>>>(h, post_ln_w, post_ln_b, out);
}